// round 13
// baseline (speedup 1.0000x reference)
#include <cuda_runtime.h>
#include <cuda_fp16.h>
#include <cstdint>

#define HID 128
#define DT_MAXF 0.125f
#define NSTEPS 8
#define THREADS 256
#define MAXN (1<<18)
#define APITCH 272              // bytes per A row (128 fp16 + pad)

__device__ int g_parts[1024][16];
__device__ int g_cursor[16];
__device__ int g_perm[MAXN];

// ---- smem byte offsets ----
#define OFF_A0HI 0              // 34816
#define OFF_A0LO 34816          // 34816
#define OFF_CPRE 69632          // 65536: cpre f32 [k][m]
#define OFF_PSUM 135168         // 24576: psum f32 [4 ngroups][128 m][12]
#define OFF_W1X  159744         // 2048 : f32 [k][4] = W1[64+q][k]
#define SMEM_BYTES 161792

#define FCPRE (OFF_CPRE/4)
#define FPSUM (OFF_PSUM/4)
#define FW1X  (OFF_W1X/4)

__device__ __forceinline__ float ftanh(float x){
    float e = __expf(2.0f*x);
    return 1.0f - __fdividef(2.0f, e+1.0f);
}
__device__ __forceinline__ uint32_t packh(float a, float b){
    __half2 t = __floats2half2_rn(a, b);
    return *reinterpret_cast<uint32_t*>(&t);
}
__device__ __forceinline__ void splith(float v, float& hi, float& lo){
    hi = __half2float(__float2half_rn(v));
    lo = v - hi;
}
__device__ __forceinline__ uint32_t hmul2u(uint32_t a, uint32_t b){
    __half2 r = __hmul2(*reinterpret_cast<__half2*>(&a), *reinterpret_cast<__half2*>(&b));
    return *reinterpret_cast<uint32_t*>(&r);
}
__device__ __forceinline__ void mma16816(float d[4], const uint32_t a[4], const uint32_t b[2]){
    asm volatile(
        "mma.sync.aligned.m16n8k16.row.col.f32.f16.f16.f32 "
        "{%0,%1,%2,%3}, {%4,%5,%6,%7}, {%8,%9}, {%0,%1,%2,%3};"
        : "+f"(d[0]), "+f"(d[1]), "+f"(d[2]), "+f"(d[3])
        : "r"(a[0]), "r"(a[1]), "r"(a[2]), "r"(a[3]), "r"(b[0]), "r"(b[1]));
}
__device__ __forceinline__ void ldmat4(uint32_t a[4], uint32_t addr){
    asm volatile("ldmatrix.sync.aligned.m8n8.x4.shared.b16 {%0,%1,%2,%3}, [%4];"
        : "=r"(a[0]), "=r"(a[1]), "=r"(a[2]), "=r"(a[3]) : "r"(addr) : "memory");
}

// Forward GEMM phase + fused epilogue. Warp tile 64m x 32n.
// MODE 0: tanh(d+b2)*W3 -> psum cols 0..2 ; MODE 1: same + capture g2
template<int MODE>
__device__ __forceinline__ void gemm_fwd(float* smf, uint32_t sb,
        int lane, int tig, int g, int mg, int ng,
        const uint32_t (&bhh)[4][8][2], uint32_t (&g2p)[4][4][2],
        const float (&b2r)[4][2], const float (&w3r)[4][2][3])
{
    const uint32_t arow0 = sb + OFF_A0HI + (uint32_t)(mg*64 + (lane & 15))*APITCH
                         + ((lane & 16) ? 16u : 0u);
#pragma unroll
    for (int mt = 0; mt < 4; mt++){
        uint32_t ab = arow0 + (uint32_t)(mt*16)*APITCH;
        float d[4][4];
#pragma unroll
        for (int nt=0;nt<4;nt++){ d[nt][0]=0.f; d[nt][1]=0.f; d[nt][2]=0.f; d[nt][3]=0.f; }
#pragma unroll
        for (int kt = 0; kt < 8; kt++){
            uint32_t ah[4], al[4];
            ldmat4(ah, ab + kt*32);
            ldmat4(al, ab + 34816u + kt*32);
#pragma unroll
            for (int nt = 0; nt < 4; nt++){
                mma16816(d[nt], ah, bhh[nt][kt]);
                mma16816(d[nt], al, bhh[nt][kt]);
            }
        }
        float s[2][3] = {{0.f,0.f,0.f},{0.f,0.f,0.f}};
#pragma unroll
        for (int nt = 0; nt < 4; nt++){
#pragma unroll
            for (int rh = 0; rh < 2; rh++){
                float ng2[2];
#pragma unroll
                for (int cj = 0; cj < 2; cj++){
                    float hv = ftanh(d[nt][rh*2+cj] + b2r[nt][cj]);
                    ng2[cj] = fmaf(-hv, hv, 1.f);
                    s[rh][0] = fmaf(hv, w3r[nt][cj][0], s[rh][0]);
                    s[rh][1] = fmaf(hv, w3r[nt][cj][1], s[rh][1]);
                    s[rh][2] = fmaf(hv, w3r[nt][cj][2], s[rh][2]);
                }
                if (MODE == 1){
                    __half2 p = __floats2half2_rn(ng2[0], ng2[1]);
                    g2p[mt][nt][rh] = *reinterpret_cast<uint32_t*>(&p);
                }
            }
        }
#pragma unroll
        for (int rh = 0; rh < 2; rh++)
#pragma unroll
        for (int o = 0; o < 3; o++){
            float v = s[rh][o];
            v += __shfl_xor_sync(0xffffffffu, v, 1);
            v += __shfl_xor_sync(0xffffffffu, v, 2);
            s[rh][o] = v;
        }
        if (tig == 0){
            int row0 = mg*64 + mt*16 + g;
            float* p0 = smf + FPSUM + ng*1536 + row0*12;
            p0[0]=s[0][0]; p0[1]=s[0][1]; p0[2]=s[0][2];
            float* p1 = p0 + 8*12;
            p1[0]=s[1][0]; p1[1]=s[1][1]; p1[2]=s[1][2];
        }
    }
}

// Fused tangent GEMM: A = g1 (staged once), B_j = hmul2(W2_frag, w1x_j_frag) on the fly.
// NJ directions starting at JB; epilogue (d*g2)*W3 -> psum cols (JB+j)*3 .. +2
template<int NJ, int JB>
__device__ __forceinline__ void gemm_tan(float* smf, uint32_t sb,
        int lane, int tig, int g, int mg, int ng,
        const uint32_t (&bhh)[4][8][2], const uint32_t (&w1xp)[3][8][2],
        const uint32_t (&g2p)[4][4][2], const float (&w3r)[4][2][3])
{
    const uint32_t arow0 = sb + OFF_A0HI + (uint32_t)(mg*64 + (lane & 15))*APITCH
                         + ((lane & 16) ? 16u : 0u);
#pragma unroll
    for (int mt = 0; mt < 4; mt++){
        uint32_t ab = arow0 + (uint32_t)(mt*16)*APITCH;
        float d[NJ][4][4];
#pragma unroll
        for (int j=0;j<NJ;j++)
#pragma unroll
        for (int nt=0;nt<4;nt++){ d[j][nt][0]=0.f; d[j][nt][1]=0.f; d[j][nt][2]=0.f; d[j][nt][3]=0.f; }
#pragma unroll
        for (int kt = 0; kt < 8; kt++){
            uint32_t ah[4], al[4];
            ldmat4(ah, ab + kt*32);
            ldmat4(al, ab + 34816u + kt*32);
#pragma unroll
            for (int j = 0; j < NJ; j++){
                uint32_t wj0 = w1xp[JB+j][kt][0], wj1 = w1xp[JB+j][kt][1];
#pragma unroll
                for (int nt = 0; nt < 4; nt++){
                    uint32_t bb[2];
                    bb[0] = hmul2u(bhh[nt][kt][0], wj0);
                    bb[1] = hmul2u(bhh[nt][kt][1], wj1);
                    mma16816(d[j][nt], ah, bb);
                    mma16816(d[j][nt], al, bb);
                }
            }
        }
        float s[NJ][2][3];
#pragma unroll
        for (int j=0;j<NJ;j++)
#pragma unroll
        for (int rh=0;rh<2;rh++){ s[j][rh][0]=0.f; s[j][rh][1]=0.f; s[j][rh][2]=0.f; }
#pragma unroll
        for (int nt = 0; nt < 4; nt++)
#pragma unroll
        for (int rh = 0; rh < 2; rh++){
            uint32_t u = g2p[mt][nt][rh];
            __half2 hv2 = *reinterpret_cast<__half2*>(&u);
            float g2v[2] = { __low2float(hv2), __high2float(hv2) };
#pragma unroll
            for (int j = 0; j < NJ; j++)
#pragma unroll
            for (int cj = 0; cj < 2; cj++){
                float use = d[j][nt][rh*2+cj] * g2v[cj];
                s[j][rh][0] = fmaf(use, w3r[nt][cj][0], s[j][rh][0]);
                s[j][rh][1] = fmaf(use, w3r[nt][cj][1], s[j][rh][1]);
                s[j][rh][2] = fmaf(use, w3r[nt][cj][2], s[j][rh][2]);
            }
        }
#pragma unroll
        for (int j = 0; j < NJ; j++)
#pragma unroll
        for (int rh = 0; rh < 2; rh++)
#pragma unroll
        for (int o = 0; o < 3; o++){
            float v = s[j][rh][o];
            v += __shfl_xor_sync(0xffffffffu, v, 1);
            v += __shfl_xor_sync(0xffffffffu, v, 2);
            s[j][rh][o] = v;
        }
        if (tig == 0){
            int row0 = mg*64 + mt*16 + g;
            float* p0 = smf + FPSUM + ng*1536 + row0*12;
            float* p1 = p0 + 8*12;
#pragma unroll
            for (int j = 0; j < NJ; j++)
#pragma unroll
            for (int o = 0; o < 3; o++){
                p0[(JB+j)*3+o] = s[j][0][o];
                p1[(JB+j)*3+o] = s[j][1][o];
            }
        }
    }
}

// ---- bucketing: 3 kernels ----
__device__ __forceinline__ int steps_needed(float off){
    float a = fabsf(off);
    int k = (int)ceilf(a*8.0f);
    return k > NSTEPS ? NSTEPS : k;
}
__global__ void k_hist(const float* t1, const float* t2, int n){
    __shared__ int lh[16];
    if (threadIdx.x < 16) lh[threadIdx.x] = 0;
    __syncthreads();
    int i = blockIdx.x*blockDim.x + threadIdx.x;
    if (i < n) atomicAdd(&lh[steps_needed(t1[i]-t2[i])], 1);
    __syncthreads();
    if (threadIdx.x < 16) g_parts[blockIdx.x][threadIdx.x] = lh[threadIdx.x];
}
__global__ void k_prefix(int nb){
    __shared__ int tot[16];
    int b = threadIdx.x;
    if (b < 16){
        int s = 0;
        for (int blk = 0; blk < nb; blk++) s += g_parts[blk][b];
        tot[b] = s;
    }
    __syncthreads();
    if (threadIdx.x == 0){
        int s = 0;
#pragma unroll
        for (int q = 0; q <= NSTEPS; q++){ g_cursor[q] = s; s += tot[q]; }
    }
}
__global__ void k_scatter(const float* t1, const float* t2, int n){
    __shared__ int lh[16], lb[16];
    if (threadIdx.x < 16) lh[threadIdx.x] = 0;
    __syncthreads();
    int i = blockIdx.x*blockDim.x + threadIdx.x;
    int k = 0, loc = 0; bool v = (i < n);
    if (v){ k = steps_needed(t1[i]-t2[i]); loc = atomicAdd(&lh[k], 1); }
    __syncthreads();
    if (threadIdx.x < 16 && lh[threadIdx.x])
        lb[threadIdx.x] = atomicAdd(&g_cursor[threadIdx.x], lh[threadIdx.x]);
    __syncthreads();
    if (v) g_perm[lb[k]+loc] = i;
}

__global__ void __launch_bounds__(THREADS, 1)
velwarp_kernel(const float* __restrict__ code_g, const float* __restrict__ pos_g,
               const float* __restrict__ t1_g, const float* __restrict__ t2_g,
               const float* __restrict__ W1_g, const float* __restrict__ b1_g,
               const float* __restrict__ W2_g, const float* __restrict__ b2_g,
               const float* __restrict__ W3_g, const float* __restrict__ b3_g,
               float* __restrict__ out, int n)
{
    extern __shared__ char smc[];
    float* smf = (float*)smc;
    uint32_t sb;
    asm("{ .reg .u64 t; cvta.to.shared.u64 t, %1; cvt.u32.u64 %0, t; }" : "=r"(sb) : "l"(smc));

    const int tid  = threadIdx.x;
    const int lane = tid & 31;
    const int g    = lane >> 2;
    const int tig  = lane & 3;
    const int wslot = tid >> 5;          // 0..7
    const int mg   = wslot >> 2;         // m group: rows [mg*64, +64)
    const int ng   = wslot & 3;          // n group: cols [ng*32, +32)
    const int m    = tid & 127;          // point in CTA
    const int kh   = tid >> 7;           // k half 0..1
    const int pbase = blockIdx.x * 128;
    const int slot = pbase + m;
    const int myp = (slot < n) ? g_perm[slot] : -1;

    // ---- prologue: W1 staged temporarily into A0 region; cpre -> smem ----
    {
        float* w1tmp = (float*)(smc + OFF_A0HI);
        for (int i = tid; i < 64*HID; i += THREADS) w1tmp[i] = W1_g[i];
        if (tid < HID){
#pragma unroll
            for (int kk=0;kk<4;kk++) smf[FW1X + tid*4 + kk] = W1_g[(64+kk)*HID + tid];
        }
        __syncthreads();
        float acc[64];
#pragma unroll
        for (int i=0;i<64;i++) acc[i] = b1_g[kh*64 + i];
#pragma unroll 1
        for (int c0=0;c0<64;c0+=16){
            float cd[16];
#pragma unroll
            for (int u=0;u<16;u++)
                cd[u] = (myp>=0) ? code_g[(size_t)myp*64 + c0 + u] : 0.f;
#pragma unroll
            for (int u=0;u<16;u++){
                float cc = cd[u];
                const float* wr = w1tmp + (c0+u)*HID + kh*64;
#pragma unroll
                for (int i=0;i<64;i+=4){
                    float4 w = *(const float4*)(wr + i);
                    acc[i]   = fmaf(cc,w.x,acc[i]);
                    acc[i+1] = fmaf(cc,w.y,acc[i+1]);
                    acc[i+2] = fmaf(cc,w.z,acc[i+2]);
                    acc[i+3] = fmaf(cc,w.w,acc[i+3]);
                }
            }
        }
        __syncthreads();
#pragma unroll
        for (int i=0;i<64;i++) smf[FCPRE + (kh*64+i)*128 + m] = acc[i];
        __syncthreads();
    }

    // ---- W2 hi fragments + w1x packed fragments (registers) ----
    uint32_t bhh[4][8][2];
#pragma unroll
    for (int nt=0;nt<4;nt++)
#pragma unroll
    for (int kt=0;kt<8;kt++){
        int nn = ng*32 + nt*8 + g;
        int k0 = kt*16 + tig*2;
        float f0=W2_g[(size_t)k0*HID+nn],     f1=W2_g[(size_t)(k0+1)*HID+nn];
        float f2=W2_g[(size_t)(k0+8)*HID+nn], f3=W2_g[(size_t)(k0+9)*HID+nn];
        bhh[nt][kt][0]=packh(f0,f1); bhh[nt][kt][1]=packh(f2,f3);
    }
    uint32_t w1xp[3][8][2];
#pragma unroll
    for (int j=0;j<3;j++)
#pragma unroll
    for (int kt=0;kt<8;kt++){
        int k0 = kt*16 + tig*2;
        w1xp[j][kt][0] = packh(smf[FW1X + k0*4 + j],     smf[FW1X + (k0+1)*4 + j]);
        w1xp[j][kt][1] = packh(smf[FW1X + (k0+8)*4 + j], smf[FW1X + (k0+9)*4 + j]);
    }
    float b2r[4][2], w3r[4][2][3];
#pragma unroll
    for (int nt=0;nt<4;nt++)
#pragma unroll
    for (int cj=0;cj<2;cj++){
        int nn = ng*32 + nt*8 + tig*2 + cj;
        b2r[nt][cj] = b2_g[nn];
        w3r[nt][cj][0]=W3_g[nn*3+0]; w3r[nt][cj][1]=W3_g[nn*3+1]; w3r[nt][cj][2]=W3_g[nn*3+2];
    }
    const float b3x=b3_g[0], b3y=b3_g[1], b3z=b3_g[2];

    float px=0.f,py=0.f,pz=0.f,tt=0.f,off=0.f;
    float D[9] = {1,0,0, 0,1,0, 0,0,1};
    if (myp>=0){
        px = pos_g[(size_t)myp*3+0];
        py = pos_g[(size_t)myp*3+1];
        pz = pos_g[(size_t)myp*3+2];
        tt = t1_g[myp];
        off = tt - t2_g[myp];
    }

    uint32_t g2p[4][4][2];

#define LAYER1_STAGE(X0,X1,X2,X3) do { \
        _Pragma("unroll") \
        for (int i2=0;i2<8;i2++){ \
            uint32_t hi4[4], lo4[4]; \
            _Pragma("unroll") \
            for (int u2=0;u2<4;u2++){ \
                int k0 = kh*64 + i2*8 + u2*2; \
                float a0 = smf[FCPRE + k0*128 + m]; \
                float a1 = smf[FCPRE + (k0+1)*128 + m]; \
                float4 w0 = *(const float4*)(smf + FW1X + k0*4); \
                float4 w1 = *(const float4*)(smf + FW1X + (k0+1)*4); \
                a0=fmaf((X0),w0.x,a0); a0=fmaf((X1),w0.y,a0); a0=fmaf((X2),w0.z,a0); a0=fmaf((X3),w0.w,a0); \
                a1=fmaf((X0),w1.x,a1); a1=fmaf((X1),w1.y,a1); a1=fmaf((X2),w1.z,a1); a1=fmaf((X3),w1.w,a1); \
                float hv0=ftanh(a0), hv1=ftanh(a1); \
                float ha,la,hb,lb; splith(hv0,ha,la); splith(hv1,hb,lb); \
                hi4[u2]=packh(ha,hb); lo4[u2]=packh(la,lb); \
            } \
            *(uint4*)(smc + OFF_A0HI + m*APITCH + (kh*64+i2*8)*2) = make_uint4(hi4[0],hi4[1],hi4[2],hi4[3]); \
            *(uint4*)(smc + OFF_A0LO + m*APITCH + (kh*64+i2*8)*2) = make_uint4(lo4[0],lo4[1],lo4[2],lo4[3]); \
        } \
    } while(0)

    // in-place A0: h -> g1 = 1 - h^2 (split hi/lo)
#define G1_CONVERT() do { \
        _Pragma("unroll") \
        for (int i2=0;i2<8;i2++){ \
            uint4 hu = *(const uint4*)(smc + OFF_A0HI + m*APITCH + (kh*64+i2*8)*2); \
            uint4 lu = *(const uint4*)(smc + OFF_A0LO + m*APITCH + (kh*64+i2*8)*2); \
            uint32_t hw[4]={hu.x,hu.y,hu.z,hu.w}, lw[4]={lu.x,lu.y,lu.z,lu.w}; \
            uint32_t hi4[4], lo4[4]; \
            _Pragma("unroll") \
            for (int u2=0;u2<4;u2++){ \
                __half2 hh = *reinterpret_cast<__half2*>(&hw[u2]); \
                __half2 ll = *reinterpret_cast<__half2*>(&lw[u2]); \
                float h0 = __low2float(hh) + __low2float(ll); \
                float h1 = __high2float(hh) + __high2float(ll); \
                float g0 = fmaf(-h0,h0,1.f), g1v = fmaf(-h1,h1,1.f); \
                float ha,la,hb,lb; splith(g0,ha,la); splith(g1v,hb,lb); \
                hi4[u2]=packh(ha,hb); lo4[u2]=packh(la,lb); \
            } \
            *(uint4*)(smc + OFF_A0HI + m*APITCH + (kh*64+i2*8)*2) = make_uint4(hi4[0],hi4[1],hi4[2],hi4[3]); \
            *(uint4*)(smc + OFF_A0LO + m*APITCH + (kh*64+i2*8)*2) = make_uint4(lo4[0],lo4[1],lo4[2],lo4[3]); \
        } \
    } while(0)

#define SUMC(col) ({ float _s = 0.f; \
        _Pragma("unroll") \
        for (int gg=0;gg<4;gg++) _s += smf[FPSUM + gg*1536 + m*12 + (col)]; \
        _s; })

#pragma unroll 1
    for (int s = 0; s < NSTEPS; s++){
        if (!__syncthreads_or(off != 0.0f)) break;

        // ---- fwd1 ----
        LAYER1_STAGE(px, py, pz, tt);
        __syncthreads();
        gemm_fwd<0>(smf, sb, lane, tig, g, mg, ng, bhh, g2p, b2r, w3r);
        __syncthreads();
        float dt = copysignf(fminf(fabsf(off), DT_MAXF), off);
        float qx = fmaf(-0.5f*dt, SUMC(0)+b3x, px);
        float qy = fmaf(-0.5f*dt, SUMC(1)+b3y, py);
        float qz = fmaf(-0.5f*dt, SUMC(2)+b3z, pz);
        float qt = tt - 0.5f*dt;

        // ---- fwd2 (captures g2) ----
        LAYER1_STAGE(qx, qy, qz, qt);
        __syncthreads();
        gemm_fwd<1>(smf, sb, lane, tig, g, mg, ng, bhh, g2p, b2r, w3r);
        __syncthreads();
        float vx = SUMC(0)+b3x, vy = SUMC(1)+b3y, vz = SUMC(2)+b3z;

        // ---- tangents: A0 h->g1 once, then 2 fused GEMM phases ----
        G1_CONVERT();
        __syncthreads();
        gemm_tan<2,0>(smf, sb, lane, tig, g, mg, ng, bhh, w1xp, g2p, w3r);
        __syncthreads();
        gemm_tan<1,2>(smf, sb, lane, tig, g, mg, ng, bhh, w1xp, g2p, w3r);
        __syncthreads();
        float jac[9];
#pragma unroll
        for (int q=0;q<9;q++) jac[q] = SUMC(q);

        float dr[9];
#pragma unroll
        for (int o=0;o<3;o++)
#pragma unroll
            for (int c=0;c<3;c++)
                dr[o*3+c] = jac[0+o]*D[0*3+c] + jac[3+o]*D[1*3+c] + jac[6+o]*D[2*3+c];
#pragma unroll
        for (int q=0;q<9;q++) D[q] = fmaf(-dt, dr[q], D[q]);
        px = fmaf(-dt, vx, px);
        py = fmaf(-dt, vy, py);
        pz = fmaf(-dt, vz, pz);
        tt -= dt; off -= dt;
    }

    if (kh == 0 && myp >= 0){
        out[(size_t)myp*3+0]=px; out[(size_t)myp*3+1]=py; out[(size_t)myp*3+2]=pz;
        float* od = out + (size_t)n*3 + (size_t)myp*9;
#pragma unroll
        for (int q=0;q<9;q++) od[q] = D[q];
    }
}

extern "C" void kernel_launch(void* const* d_in, const int* in_sizes, int n_in,
                              void* d_out, int out_size)
{
    const float* code = (const float*)d_in[0];
    const float* pos  = (const float*)d_in[1];
    const float* t1   = (const float*)d_in[2];
    const float* t2   = (const float*)d_in[3];
    const float* W1   = (const float*)d_in[4];
    const float* b1   = (const float*)d_in[5];
    const float* W2   = (const float*)d_in[6];
    const float* b2   = (const float*)d_in[7];
    const float* W3   = (const float*)d_in[8];
    const float* b3   = (const float*)d_in[9];
    const int n = in_sizes[2];
    const int nb = (n + 255)/256;

    k_hist<<<nb,256>>>(t1,t2,n);
    k_prefix<<<1,32>>>(nb);
    k_scatter<<<nb,256>>>(t1,t2,n);

    cudaFuncSetAttribute(velwarp_kernel,
                         cudaFuncAttributeMaxDynamicSharedMemorySize, SMEM_BYTES);
    velwarp_kernel<<<(n+127)/128, THREADS, SMEM_BYTES>>>(
        code, pos, t1, t2, W1, b1, W2, b2, W3, b3, (float*)d_out, n);
}

// round 14
// speedup vs baseline: 1.1935x; 1.1935x over previous
#include <cuda_runtime.h>
#include <cuda_fp16.h>
#include <cstdint>

#define HID 128
#define DT_MAXF 0.125f
#define NSTEPS 8
#define THREADS 128
#define PPC 64                  // points per CTA
#define MAXN (1<<18)
#define APITCH 272              // bytes per A row (128 fp16 + pad)

__device__ int g_parts[1024][16];
__device__ int g_cursor[16];
__device__ int g_perm[MAXN];

// ---- smem byte offsets (per-CTA ~83KB -> 2 CTAs/SM) ----
#define OFF_A0HI 0              // 17408 (64 rows x 272B)
#define OFF_A0LO 17408          // 17408
#define OFF_CPRE 34816          // 32768: cpre f32 [128 k][64 m]
#define OFF_PSUM 67584          // 12288: psum f32 [4 ng][64 m][12]
#define OFF_W1X  79872          // 2048 : f32 [k][4] = W1[64+q][k]
#define OFF_W1XP 81920          // 1024 : packed half2 table [3][8][4 tig][2]
#define SMEM_BYTES 82944

#define FCPRE (OFF_CPRE/4)
#define FPSUM (OFF_PSUM/4)
#define FW1X  (OFF_W1X/4)
#define ALO_DELTA 17408u

__device__ __forceinline__ float ftanh(float x){
    float e = __expf(2.0f*x);
    return 1.0f - __fdividef(2.0f, e+1.0f);
}
__device__ __forceinline__ uint32_t packh(float a, float b){
    __half2 t = __floats2half2_rn(a, b);
    return *reinterpret_cast<uint32_t*>(&t);
}
__device__ __forceinline__ void splith(float v, float& hi, float& lo){
    hi = __half2float(__float2half_rn(v));
    lo = v - hi;
}
__device__ __forceinline__ uint32_t hmul2u(uint32_t a, uint32_t b){
    __half2 r = __hmul2(*reinterpret_cast<__half2*>(&a), *reinterpret_cast<__half2*>(&b));
    return *reinterpret_cast<uint32_t*>(&r);
}
__device__ __forceinline__ void mma16816(float d[4], const uint32_t a[4], const uint32_t b[2]){
    asm volatile(
        "mma.sync.aligned.m16n8k16.row.col.f32.f16.f16.f32 "
        "{%0,%1,%2,%3}, {%4,%5,%6,%7}, {%8,%9}, {%0,%1,%2,%3};"
        : "+f"(d[0]), "+f"(d[1]), "+f"(d[2]), "+f"(d[3])
        : "r"(a[0]), "r"(a[1]), "r"(a[2]), "r"(a[3]), "r"(b[0]), "r"(b[1]));
}
__device__ __forceinline__ void ldmat4(uint32_t a[4], uint32_t addr){
    asm volatile("ldmatrix.sync.aligned.m8n8.x4.shared.b16 {%0,%1,%2,%3}, [%4];"
        : "=r"(a[0]), "=r"(a[1]), "=r"(a[2]), "=r"(a[3]) : "r"(addr) : "memory");
}

// Forward GEMM phase + fused epilogue. Warp tile: 64m x 32n (warp = ng).
// MODE 0: tanh(d+b2)*W3 -> psum cols 0..2 ; MODE 1: same + capture g2
template<int MODE>
__device__ __forceinline__ void gemm_fwd(float* smf, uint32_t sb,
        int lane, int tig, int g, int ng,
        const uint32_t (&bhh)[4][8][2], uint32_t (&g2p)[4][4][2],
        const float (&b2r)[4][2], const float (&w3r)[4][2][3])
{
    const uint32_t arow0 = sb + OFF_A0HI + (uint32_t)(lane & 15)*APITCH
                         + ((lane & 16) ? 16u : 0u);
#pragma unroll
    for (int mt = 0; mt < 4; mt++){
        uint32_t ab = arow0 + (uint32_t)(mt*16)*APITCH;
        float d[4][4];
#pragma unroll
        for (int nt=0;nt<4;nt++){ d[nt][0]=0.f; d[nt][1]=0.f; d[nt][2]=0.f; d[nt][3]=0.f; }
#pragma unroll
        for (int kt = 0; kt < 8; kt++){
            uint32_t ah[4], al[4];
            ldmat4(ah, ab + kt*32);
            ldmat4(al, ab + ALO_DELTA + kt*32);
#pragma unroll
            for (int nt = 0; nt < 4; nt++){
                mma16816(d[nt], ah, bhh[nt][kt]);
                mma16816(d[nt], al, bhh[nt][kt]);
            }
        }
        float s[2][3] = {{0.f,0.f,0.f},{0.f,0.f,0.f}};
#pragma unroll
        for (int nt = 0; nt < 4; nt++){
#pragma unroll
            for (int rh = 0; rh < 2; rh++){
                float ng2[2];
#pragma unroll
                for (int cj = 0; cj < 2; cj++){
                    float hv = ftanh(d[nt][rh*2+cj] + b2r[nt][cj]);
                    ng2[cj] = fmaf(-hv, hv, 1.f);
                    s[rh][0] = fmaf(hv, w3r[nt][cj][0], s[rh][0]);
                    s[rh][1] = fmaf(hv, w3r[nt][cj][1], s[rh][1]);
                    s[rh][2] = fmaf(hv, w3r[nt][cj][2], s[rh][2]);
                }
                if (MODE == 1){
                    __half2 p = __floats2half2_rn(ng2[0], ng2[1]);
                    g2p[mt][nt][rh] = *reinterpret_cast<uint32_t*>(&p);
                }
            }
        }
#pragma unroll
        for (int rh = 0; rh < 2; rh++)
#pragma unroll
        for (int o = 0; o < 3; o++){
            float v = s[rh][o];
            v += __shfl_xor_sync(0xffffffffu, v, 1);
            v += __shfl_xor_sync(0xffffffffu, v, 2);
            s[rh][o] = v;
        }
        if (tig == 0){
            int row0 = mt*16 + g;
            float* p0 = smf + FPSUM + ng*768 + row0*12;
            p0[0]=s[0][0]; p0[1]=s[0][1]; p0[2]=s[0][2];
            float* p1 = p0 + 8*12;
            p1[0]=s[1][0]; p1[1]=s[1][1]; p1[2]=s[1][2];
        }
    }
}

// Tangent GEMM, one direction J: A = g1 (in A0), B_j = hmul2(W2_frag, w1xp_frag)
// with w1xp read from packed smem table. Epilogue (d*g2)*W3 -> psum cols J*3..+2.
__device__ __forceinline__ void gemm_tan(float* smf, uint32_t sb, int J,
        int lane, int tig, int g, int ng,
        const uint32_t (&bhh)[4][8][2], const uint32_t* w1xps,
        const uint32_t (&g2p)[4][4][2], const float (&w3r)[4][2][3])
{
    const uint32_t arow0 = sb + OFF_A0HI + (uint32_t)(lane & 15)*APITCH
                         + ((lane & 16) ? 16u : 0u);
    uint32_t wjf[8][2];
#pragma unroll
    for (int kt=0;kt<8;kt++){
        const uint32_t* p = w1xps + ((J*8 + kt)*4 + tig)*2;
        wjf[kt][0] = p[0]; wjf[kt][1] = p[1];
    }
#pragma unroll
    for (int mt = 0; mt < 4; mt++){
        uint32_t ab = arow0 + (uint32_t)(mt*16)*APITCH;
        float d[4][4];
#pragma unroll
        for (int nt=0;nt<4;nt++){ d[nt][0]=0.f; d[nt][1]=0.f; d[nt][2]=0.f; d[nt][3]=0.f; }
#pragma unroll
        for (int kt = 0; kt < 8; kt++){
            uint32_t ah[4], al[4];
            ldmat4(ah, ab + kt*32);
            ldmat4(al, ab + ALO_DELTA + kt*32);
#pragma unroll
            for (int nt = 0; nt < 4; nt++){
                uint32_t bb[2];
                bb[0] = hmul2u(bhh[nt][kt][0], wjf[kt][0]);
                bb[1] = hmul2u(bhh[nt][kt][1], wjf[kt][1]);
                mma16816(d[nt], ah, bb);
                mma16816(d[nt], al, bb);
            }
        }
        float s[2][3] = {{0.f,0.f,0.f},{0.f,0.f,0.f}};
#pragma unroll
        for (int nt = 0; nt < 4; nt++)
#pragma unroll
        for (int rh = 0; rh < 2; rh++){
            uint32_t u = g2p[mt][nt][rh];
            __half2 hv2 = *reinterpret_cast<__half2*>(&u);
            float g2v[2] = { __low2float(hv2), __high2float(hv2) };
#pragma unroll
            for (int cj = 0; cj < 2; cj++){
                float use = d[nt][rh*2+cj] * g2v[cj];
                s[rh][0] = fmaf(use, w3r[nt][cj][0], s[rh][0]);
                s[rh][1] = fmaf(use, w3r[nt][cj][1], s[rh][1]);
                s[rh][2] = fmaf(use, w3r[nt][cj][2], s[rh][2]);
            }
        }
#pragma unroll
        for (int rh = 0; rh < 2; rh++)
#pragma unroll
        for (int o = 0; o < 3; o++){
            float v = s[rh][o];
            v += __shfl_xor_sync(0xffffffffu, v, 1);
            v += __shfl_xor_sync(0xffffffffu, v, 2);
            s[rh][o] = v;
        }
        if (tig == 0){
            int row0 = mt*16 + g;
            float* p0 = smf + FPSUM + ng*768 + row0*12;
            float* p1 = p0 + 8*12;
#pragma unroll
            for (int o = 0; o < 3; o++){
                p0[J*3+o] = s[0][o];
                p1[J*3+o] = s[1][o];
            }
        }
    }
}

// ---- bucketing: 3 kernels ----
__device__ __forceinline__ int steps_needed(float off){
    float a = fabsf(off);
    int k = (int)ceilf(a*8.0f);
    return k > NSTEPS ? NSTEPS : k;
}
__global__ void k_hist(const float* t1, const float* t2, int n){
    __shared__ int lh[16];
    if (threadIdx.x < 16) lh[threadIdx.x] = 0;
    __syncthreads();
    int i = blockIdx.x*blockDim.x + threadIdx.x;
    if (i < n) atomicAdd(&lh[steps_needed(t1[i]-t2[i])], 1);
    __syncthreads();
    if (threadIdx.x < 16) g_parts[blockIdx.x][threadIdx.x] = lh[threadIdx.x];
}
__global__ void k_prefix(int nb){
    __shared__ int tot[16];
    int b = threadIdx.x;
    if (b < 16){
        int s = 0;
        for (int blk = 0; blk < nb; blk++) s += g_parts[blk][b];
        tot[b] = s;
    }
    __syncthreads();
    if (threadIdx.x == 0){
        int s = 0;
#pragma unroll
        for (int q = 0; q <= NSTEPS; q++){ g_cursor[q] = s; s += tot[q]; }
    }
}
__global__ void k_scatter(const float* t1, const float* t2, int n){
    __shared__ int lh[16], lb[16];
    if (threadIdx.x < 16) lh[threadIdx.x] = 0;
    __syncthreads();
    int i = blockIdx.x*blockDim.x + threadIdx.x;
    int k = 0, loc = 0; bool v = (i < n);
    if (v){ k = steps_needed(t1[i]-t2[i]); loc = atomicAdd(&lh[k], 1); }
    __syncthreads();
    if (threadIdx.x < 16 && lh[threadIdx.x])
        lb[threadIdx.x] = atomicAdd(&g_cursor[threadIdx.x], lh[threadIdx.x]);
    __syncthreads();
    if (v) g_perm[lb[k]+loc] = i;
}

__global__ void __launch_bounds__(THREADS, 2)
velwarp_kernel(const float* __restrict__ code_g, const float* __restrict__ pos_g,
               const float* __restrict__ t1_g, const float* __restrict__ t2_g,
               const float* __restrict__ W1_g, const float* __restrict__ b1_g,
               const float* __restrict__ W2_g, const float* __restrict__ b2_g,
               const float* __restrict__ W3_g, const float* __restrict__ b3_g,
               float* __restrict__ out, int n)
{
    extern __shared__ char smc[];
    float* smf = (float*)smc;
    uint32_t sb;
    asm("{ .reg .u64 t; cvta.to.shared.u64 t, %1; cvt.u32.u64 %0, t; }" : "=r"(sb) : "l"(smc));

    const int tid  = threadIdx.x;
    const int lane = tid & 31;
    const int g    = lane >> 2;
    const int tig  = lane & 3;
    const int ng   = tid >> 5;           // warp 0..3 owns cols [ng*32, +32)
    const int m    = tid & 63;           // point in CTA
    const int kh   = tid >> 6;           // k half 0..1
    const int pbase = blockIdx.x * PPC;
    const int slot = pbase + m;
    const int myp = (slot < n) ? g_perm[slot] : -1;
    uint32_t* w1xps = (uint32_t*)(smc + OFF_W1XP);

    // ---- prologue: W1 staged temporarily into A0 region; cpre -> smem ----
    {
        float* w1tmp = (float*)(smc + OFF_A0HI);   // 32768 <= 34816
        for (int i = tid; i < 64*HID; i += THREADS) w1tmp[i] = W1_g[i];
        if (tid < HID){
#pragma unroll
            for (int kk=0;kk<4;kk++) smf[FW1X + tid*4 + kk] = W1_g[(64+kk)*HID + tid];
        }
        __syncthreads();
        float acc[64];
#pragma unroll
        for (int i=0;i<64;i++) acc[i] = b1_g[kh*64 + i];
#pragma unroll 1
        for (int c0=0;c0<64;c0+=16){
            float cd[16];
#pragma unroll
            for (int u=0;u<16;u++)
                cd[u] = (myp>=0) ? code_g[(size_t)myp*64 + c0 + u] : 0.f;
#pragma unroll
            for (int u=0;u<16;u++){
                float cc = cd[u];
                const float* wr = w1tmp + (c0+u)*HID + kh*64;
#pragma unroll
                for (int i=0;i<64;i+=4){
                    float4 w = *(const float4*)(wr + i);
                    acc[i]   = fmaf(cc,w.x,acc[i]);
                    acc[i+1] = fmaf(cc,w.y,acc[i+1]);
                    acc[i+2] = fmaf(cc,w.z,acc[i+2]);
                    acc[i+3] = fmaf(cc,w.w,acc[i+3]);
                }
            }
        }
        __syncthreads();
#pragma unroll
        for (int i=0;i<64;i++) smf[FCPRE + (kh*64+i)*64 + m] = acc[i];
        // packed w1x table: entry ((j*8+kt)*4+tig)*2 + half  (96 entries x2)
        if (tid < 96){
            int j  = tid / 32;
            int kt = (tid >> 2) & 7;
            int tg = tid & 3;
            int k0 = kt*16 + tg*2;
            w1xps[((j*8+kt)*4+tg)*2 + 0] = packh(smf[FW1X + k0*4 + j],     smf[FW1X + (k0+1)*4 + j]);
            w1xps[((j*8+kt)*4+tg)*2 + 1] = packh(smf[FW1X + (k0+8)*4 + j], smf[FW1X + (k0+9)*4 + j]);
        }
        __syncthreads();
    }

    // ---- W2 hi fragments (fp16): this warp's 32 cols ----
    uint32_t bhh[4][8][2];
#pragma unroll
    for (int nt=0;nt<4;nt++)
#pragma unroll
    for (int kt=0;kt<8;kt++){
        int nn = ng*32 + nt*8 + g;
        int k0 = kt*16 + tig*2;
        float f0=W2_g[(size_t)k0*HID+nn],     f1=W2_g[(size_t)(k0+1)*HID+nn];
        float f2=W2_g[(size_t)(k0+8)*HID+nn], f3=W2_g[(size_t)(k0+9)*HID+nn];
        bhh[nt][kt][0]=packh(f0,f1); bhh[nt][kt][1]=packh(f2,f3);
    }
    float b2r[4][2], w3r[4][2][3];
#pragma unroll
    for (int nt=0;nt<4;nt++)
#pragma unroll
    for (int cj=0;cj<2;cj++){
        int nn = ng*32 + nt*8 + tig*2 + cj;
        b2r[nt][cj] = b2_g[nn];
        w3r[nt][cj][0]=W3_g[nn*3+0]; w3r[nt][cj][1]=W3_g[nn*3+1]; w3r[nt][cj][2]=W3_g[nn*3+2];
    }
    const float b3x=b3_g[0], b3y=b3_g[1], b3z=b3_g[2];

    float px=0.f,py=0.f,pz=0.f,tt=0.f,off=0.f;
    float D[9] = {1,0,0, 0,1,0, 0,0,1};
    if (myp>=0){
        px = pos_g[(size_t)myp*3+0];
        py = pos_g[(size_t)myp*3+1];
        pz = pos_g[(size_t)myp*3+2];
        tt = t1_g[myp];
        off = tt - t2_g[myp];
    }

    uint32_t g2p[4][4][2];

#define LAYER1_STAGE(X0,X1,X2,X3) do { \
        _Pragma("unroll") \
        for (int i2=0;i2<8;i2++){ \
            uint32_t hi4[4], lo4[4]; \
            _Pragma("unroll") \
            for (int u2=0;u2<4;u2++){ \
                int k0 = kh*64 + i2*8 + u2*2; \
                float a0 = smf[FCPRE + k0*64 + m]; \
                float a1 = smf[FCPRE + (k0+1)*64 + m]; \
                float4 w0 = *(const float4*)(smf + FW1X + k0*4); \
                float4 w1 = *(const float4*)(smf + FW1X + (k0+1)*4); \
                a0=fmaf((X0),w0.x,a0); a0=fmaf((X1),w0.y,a0); a0=fmaf((X2),w0.z,a0); a0=fmaf((X3),w0.w,a0); \
                a1=fmaf((X0),w1.x,a1); a1=fmaf((X1),w1.y,a1); a1=fmaf((X2),w1.z,a1); a1=fmaf((X3),w1.w,a1); \
                float hv0=ftanh(a0), hv1=ftanh(a1); \
                float ha,la,hb,lb; splith(hv0,ha,la); splith(hv1,hb,lb); \
                hi4[u2]=packh(ha,hb); lo4[u2]=packh(la,lb); \
            } \
            *(uint4*)(smc + OFF_A0HI + m*APITCH + (kh*64+i2*8)*2) = make_uint4(hi4[0],hi4[1],hi4[2],hi4[3]); \
            *(uint4*)(smc + OFF_A0LO + m*APITCH + (kh*64+i2*8)*2) = make_uint4(lo4[0],lo4[1],lo4[2],lo4[3]); \
        } \
    } while(0)

#define G1_CONVERT() do { \
        _Pragma("unroll") \
        for (int i2=0;i2<8;i2++){ \
            uint4 hu = *(const uint4*)(smc + OFF_A0HI + m*APITCH + (kh*64+i2*8)*2); \
            uint4 lu = *(const uint4*)(smc + OFF_A0LO + m*APITCH + (kh*64+i2*8)*2); \
            uint32_t hw[4]={hu.x,hu.y,hu.z,hu.w}, lw[4]={lu.x,lu.y,lu.z,lu.w}; \
            uint32_t hi4[4], lo4[4]; \
            _Pragma("unroll") \
            for (int u2=0;u2<4;u2++){ \
                __half2 hh = *reinterpret_cast<__half2*>(&hw[u2]); \
                __half2 ll = *reinterpret_cast<__half2*>(&lw[u2]); \
                float h0 = __low2float(hh) + __low2float(ll); \
                float h1 = __high2float(hh) + __high2float(ll); \
                float g0 = fmaf(-h0,h0,1.f), g1v = fmaf(-h1,h1,1.f); \
                float ha,la,hb,lb; splith(g0,ha,la); splith(g1v,hb,lb); \
                hi4[u2]=packh(ha,hb); lo4[u2]=packh(la,lb); \
            } \
            *(uint4*)(smc + OFF_A0HI + m*APITCH + (kh*64+i2*8)*2) = make_uint4(hi4[0],hi4[1],hi4[2],hi4[3]); \
            *(uint4*)(smc + OFF_A0LO + m*APITCH + (kh*64+i2*8)*2) = make_uint4(lo4[0],lo4[1],lo4[2],lo4[3]); \
        } \
    } while(0)

#define SUMC(col) ({ float _s = 0.f; \
        _Pragma("unroll") \
        for (int gg=0;gg<4;gg++) _s += smf[FPSUM + gg*768 + m*12 + (col)]; \
        _s; })

#pragma unroll 1
    for (int s = 0; s < NSTEPS; s++){
        if (!__syncthreads_or(off != 0.0f)) break;

        // ---- fwd1 ----
        LAYER1_STAGE(px, py, pz, tt);
        __syncthreads();
        gemm_fwd<0>(smf, sb, lane, tig, g, ng, bhh, g2p, b2r, w3r);
        __syncthreads();
        float dt = copysignf(fminf(fabsf(off), DT_MAXF), off);
        float qx = fmaf(-0.5f*dt, SUMC(0)+b3x, px);
        float qy = fmaf(-0.5f*dt, SUMC(1)+b3y, py);
        float qz = fmaf(-0.5f*dt, SUMC(2)+b3z, pz);
        float qt = tt - 0.5f*dt;

        // ---- fwd2 (captures g2) ----
        LAYER1_STAGE(qx, qy, qz, qt);
        __syncthreads();
        gemm_fwd<1>(smf, sb, lane, tig, g, ng, bhh, g2p, b2r, w3r);
        __syncthreads();
        float vx = SUMC(0)+b3x, vy = SUMC(1)+b3y, vz = SUMC(2)+b3z;

        // ---- tangents: A0 h->g1 once, 3 single-direction fused GEMMs ----
        G1_CONVERT();
        __syncthreads();
        gemm_tan(smf, sb, 0, lane, tig, g, ng, bhh, w1xps, g2p, w3r);
        __syncthreads();
        gemm_tan(smf, sb, 1, lane, tig, g, ng, bhh, w1xps, g2p, w3r);
        gemm_tan(smf, sb, 2, lane, tig, g, ng, bhh, w1xps, g2p, w3r);
        __syncthreads();
        float jac[9];
#pragma unroll
        for (int q=0;q<9;q++) jac[q] = SUMC(q);

        float dr[9];
#pragma unroll
        for (int o=0;o<3;o++)
#pragma unroll
            for (int c=0;c<3;c++)
                dr[o*3+c] = jac[0+o]*D[0*3+c] + jac[3+o]*D[1*3+c] + jac[6+o]*D[2*3+c];
#pragma unroll
        for (int q=0;q<9;q++) D[q] = fmaf(-dt, dr[q], D[q]);
        px = fmaf(-dt, vx, px);
        py = fmaf(-dt, vy, py);
        pz = fmaf(-dt, vz, pz);
        tt -= dt; off -= dt;
    }

    if (kh == 0 && myp >= 0){
        out[(size_t)myp*3+0]=px; out[(size_t)myp*3+1]=py; out[(size_t)myp*3+2]=pz;
        float* od = out + (size_t)n*3 + (size_t)myp*9;
#pragma unroll
        for (int q=0;q<9;q++) od[q] = D[q];
    }
}

extern "C" void kernel_launch(void* const* d_in, const int* in_sizes, int n_in,
                              void* d_out, int out_size)
{
    const float* code = (const float*)d_in[0];
    const float* pos  = (const float*)d_in[1];
    const float* t1   = (const float*)d_in[2];
    const float* t2   = (const float*)d_in[3];
    const float* W1   = (const float*)d_in[4];
    const float* b1   = (const float*)d_in[5];
    const float* W2   = (const float*)d_in[6];
    const float* b2   = (const float*)d_in[7];
    const float* W3   = (const float*)d_in[8];
    const float* b3   = (const float*)d_in[9];
    const int n = in_sizes[2];
    const int nb = (n + 255)/256;

    k_hist<<<nb,256>>>(t1,t2,n);
    k_prefix<<<1,32>>>(nb);
    k_scatter<<<nb,256>>>(t1,t2,n);

    cudaFuncSetAttribute(velwarp_kernel,
                         cudaFuncAttributeMaxDynamicSharedMemorySize, SMEM_BYTES);
    velwarp_kernel<<<(n+PPC-1)/PPC, THREADS, SMEM_BYTES>>>(
        code, pos, t1, t2, W1, b1, W2, b2, W3, b3, (float*)d_out, n);
}

// round 15
// speedup vs baseline: 1.6325x; 1.3679x over previous
#include <cuda_runtime.h>
#include <cuda_fp16.h>
#include <cstdint>

#define HID 128
#define DT_MAXF 0.125f
#define NSTEPS 8
#define THREADS 128
#define PPC 64                  // points per CTA
#define MAXN (1<<18)
#define APITCH 272              // bytes per A row (128 fp16 + pad)

__device__ int g_parts[1024][16];
__device__ int g_cursor[16];
__device__ int g_perm[MAXN];

// ---- smem byte offsets (per-CTA 64KB -> 2 CTAs/SM) ----
#define OFF_A0HI 0              // 17408 (64 rows x 272B)
#define OFF_CPRE 17408          // 32768: cpre f32 [128 k][64 m]
#define OFF_PSUM 50176          // 12288: psum f32 [4 ng][64 m][12]
#define OFF_W1X  62464          // 2048 : f32 [k][4] = W1[64+q][k]
#define OFF_W1XP 64512          // 1024 : packed half2 table [3][8][4 tig][2]
#define SMEM_BYTES 65536

#define FCPRE (OFF_CPRE/4)
#define FPSUM (OFF_PSUM/4)
#define FW1X  (OFF_W1X/4)

__device__ __forceinline__ float ftanh(float x){
    float e = __expf(2.0f*x);
    return 1.0f - __fdividef(2.0f, e+1.0f);
}
__device__ __forceinline__ uint32_t packh(float a, float b){
    __half2 t = __floats2half2_rn(a, b);
    return *reinterpret_cast<uint32_t*>(&t);
}
__device__ __forceinline__ uint32_t hmul2u(uint32_t a, uint32_t b){
    __half2 r = __hmul2(*reinterpret_cast<__half2*>(&a), *reinterpret_cast<__half2*>(&b));
    return *reinterpret_cast<uint32_t*>(&r);
}
__device__ __forceinline__ void mma16816(float d[4], const uint32_t a[4], const uint32_t b[2]){
    asm volatile(
        "mma.sync.aligned.m16n8k16.row.col.f32.f16.f16.f32 "
        "{%0,%1,%2,%3}, {%4,%5,%6,%7}, {%8,%9}, {%0,%1,%2,%3};"
        : "+f"(d[0]), "+f"(d[1]), "+f"(d[2]), "+f"(d[3])
        : "r"(a[0]), "r"(a[1]), "r"(a[2]), "r"(a[3]), "r"(b[0]), "r"(b[1]));
}
__device__ __forceinline__ void ldmat4(uint32_t a[4], uint32_t addr){
    asm volatile("ldmatrix.sync.aligned.m8n8.x4.shared.b16 {%0,%1,%2,%3}, [%4];"
        : "=r"(a[0]), "=r"(a[1]), "=r"(a[2]), "=r"(a[3]) : "r"(addr) : "memory");
}

// Forward GEMM phase + fused epilogue. Warp tile: 64m x 32n (warp = ng).
// Single-term fp16 (A=fp16(h), B=fp16(W2)), fp32 accumulate.
// MODE 0: tanh(d+b2)*W3 -> psum cols 0..2 ; MODE 1: same + capture g2
template<int MODE>
__device__ __forceinline__ void gemm_fwd(float* smf, uint32_t sb,
        int lane, int tig, int g, int ng,
        const uint32_t (&bhh)[4][8][2], uint32_t (&g2p)[4][4][2],
        const float (&b2r)[4][2], const float (&w3r)[4][2][3])
{
    const uint32_t arow0 = sb + OFF_A0HI + (uint32_t)(lane & 15)*APITCH
                         + ((lane & 16) ? 16u : 0u);
#pragma unroll
    for (int mt = 0; mt < 4; mt++){
        uint32_t ab = arow0 + (uint32_t)(mt*16)*APITCH;
        float d[4][4];
#pragma unroll
        for (int nt=0;nt<4;nt++){ d[nt][0]=0.f; d[nt][1]=0.f; d[nt][2]=0.f; d[nt][3]=0.f; }
#pragma unroll
        for (int kt = 0; kt < 8; kt++){
            uint32_t ah[4];
            ldmat4(ah, ab + kt*32);
#pragma unroll
            for (int nt = 0; nt < 4; nt++)
                mma16816(d[nt], ah, bhh[nt][kt]);
        }
        float s[2][3] = {{0.f,0.f,0.f},{0.f,0.f,0.f}};
#pragma unroll
        for (int nt = 0; nt < 4; nt++){
#pragma unroll
            for (int rh = 0; rh < 2; rh++){
                float ng2[2];
#pragma unroll
                for (int cj = 0; cj < 2; cj++){
                    float hv = ftanh(d[nt][rh*2+cj] + b2r[nt][cj]);
                    ng2[cj] = fmaf(-hv, hv, 1.f);
                    s[rh][0] = fmaf(hv, w3r[nt][cj][0], s[rh][0]);
                    s[rh][1] = fmaf(hv, w3r[nt][cj][1], s[rh][1]);
                    s[rh][2] = fmaf(hv, w3r[nt][cj][2], s[rh][2]);
                }
                if (MODE == 1){
                    __half2 p = __floats2half2_rn(ng2[0], ng2[1]);
                    g2p[mt][nt][rh] = *reinterpret_cast<uint32_t*>(&p);
                }
            }
        }
#pragma unroll
        for (int rh = 0; rh < 2; rh++)
#pragma unroll
        for (int o = 0; o < 3; o++){
            float v = s[rh][o];
            v += __shfl_xor_sync(0xffffffffu, v, 1);
            v += __shfl_xor_sync(0xffffffffu, v, 2);
            s[rh][o] = v;
        }
        if (tig == 0){
            int row0 = mt*16 + g;
            float* p0 = smf + FPSUM + ng*768 + row0*12;
            p0[0]=s[0][0]; p0[1]=s[0][1]; p0[2]=s[0][2];
            float* p1 = p0 + 8*12;
            p1[0]=s[1][0]; p1[1]=s[1][1]; p1[2]=s[1][2];
        }
    }
}

// Tangent GEMM, one direction J: A = g1 (in A0), B_j = hmul2(W2_frag, w1xp_frag),
// w1xp from packed smem table. Epilogue (d*g2)*W3 -> psum cols J*3..+2.
__device__ __forceinline__ void gemm_tan(float* smf, uint32_t sb, int J,
        int lane, int tig, int g, int ng,
        const uint32_t (&bhh)[4][8][2], const uint32_t* w1xps,
        const uint32_t (&g2p)[4][4][2], const float (&w3r)[4][2][3])
{
    const uint32_t arow0 = sb + OFF_A0HI + (uint32_t)(lane & 15)*APITCH
                         + ((lane & 16) ? 16u : 0u);
    uint32_t wjf[8][2];
#pragma unroll
    for (int kt=0;kt<8;kt++){
        const uint32_t* p = w1xps + ((J*8 + kt)*4 + tig)*2;
        wjf[kt][0] = p[0]; wjf[kt][1] = p[1];
    }
#pragma unroll
    for (int mt = 0; mt < 4; mt++){
        uint32_t ab = arow0 + (uint32_t)(mt*16)*APITCH;
        float d[4][4];
#pragma unroll
        for (int nt=0;nt<4;nt++){ d[nt][0]=0.f; d[nt][1]=0.f; d[nt][2]=0.f; d[nt][3]=0.f; }
#pragma unroll
        for (int kt = 0; kt < 8; kt++){
            uint32_t ah[4];
            ldmat4(ah, ab + kt*32);
#pragma unroll
            for (int nt = 0; nt < 4; nt++){
                uint32_t bb[2];
                bb[0] = hmul2u(bhh[nt][kt][0], wjf[kt][0]);
                bb[1] = hmul2u(bhh[nt][kt][1], wjf[kt][1]);
                mma16816(d[nt], ah, bb);
            }
        }
        float s[2][3] = {{0.f,0.f,0.f},{0.f,0.f,0.f}};
#pragma unroll
        for (int nt = 0; nt < 4; nt++)
#pragma unroll
        for (int rh = 0; rh < 2; rh++){
            uint32_t u = g2p[mt][nt][rh];
            __half2 hv2 = *reinterpret_cast<__half2*>(&u);
            float g2v[2] = { __low2float(hv2), __high2float(hv2) };
#pragma unroll
            for (int cj = 0; cj < 2; cj++){
                float use = d[nt][rh*2+cj] * g2v[cj];
                s[rh][0] = fmaf(use, w3r[nt][cj][0], s[rh][0]);
                s[rh][1] = fmaf(use, w3r[nt][cj][1], s[rh][1]);
                s[rh][2] = fmaf(use, w3r[nt][cj][2], s[rh][2]);
            }
        }
#pragma unroll
        for (int rh = 0; rh < 2; rh++)
#pragma unroll
        for (int o = 0; o < 3; o++){
            float v = s[rh][o];
            v += __shfl_xor_sync(0xffffffffu, v, 1);
            v += __shfl_xor_sync(0xffffffffu, v, 2);
            s[rh][o] = v;
        }
        if (tig == 0){
            int row0 = mt*16 + g;
            float* p0 = smf + FPSUM + ng*768 + row0*12;
            float* p1 = p0 + 8*12;
#pragma unroll
            for (int o = 0; o < 3; o++){
                p0[J*3+o] = s[0][o];
                p1[J*3+o] = s[1][o];
            }
        }
    }
}

// ---- bucketing: 3 kernels ----
__device__ __forceinline__ int steps_needed(float off){
    float a = fabsf(off);
    int k = (int)ceilf(a*8.0f);
    return k > NSTEPS ? NSTEPS : k;
}
__global__ void k_hist(const float* t1, const float* t2, int n){
    __shared__ int lh[16];
    if (threadIdx.x < 16) lh[threadIdx.x] = 0;
    __syncthreads();
    int i = blockIdx.x*blockDim.x + threadIdx.x;
    if (i < n) atomicAdd(&lh[steps_needed(t1[i]-t2[i])], 1);
    __syncthreads();
    if (threadIdx.x < 16) g_parts[blockIdx.x][threadIdx.x] = lh[threadIdx.x];
}
__global__ void k_prefix(int nb){
    __shared__ int tot[16];
    int b = threadIdx.x;
    if (b < 16){
        int s = 0;
        for (int blk = 0; blk < nb; blk++) s += g_parts[blk][b];
        tot[b] = s;
    }
    __syncthreads();
    if (threadIdx.x == 0){
        int s = 0;
#pragma unroll
        for (int q = 0; q <= NSTEPS; q++){ g_cursor[q] = s; s += tot[q]; }
    }
}
__global__ void k_scatter(const float* t1, const float* t2, int n){
    __shared__ int lh[16], lb[16];
    if (threadIdx.x < 16) lh[threadIdx.x] = 0;
    __syncthreads();
    int i = blockIdx.x*blockDim.x + threadIdx.x;
    int k = 0, loc = 0; bool v = (i < n);
    if (v){ k = steps_needed(t1[i]-t2[i]); loc = atomicAdd(&lh[k], 1); }
    __syncthreads();
    if (threadIdx.x < 16 && lh[threadIdx.x])
        lb[threadIdx.x] = atomicAdd(&g_cursor[threadIdx.x], lh[threadIdx.x]);
    __syncthreads();
    if (v) g_perm[lb[k]+loc] = i;
}

__global__ void __launch_bounds__(THREADS, 2)
velwarp_kernel(const float* __restrict__ code_g, const float* __restrict__ pos_g,
               const float* __restrict__ t1_g, const float* __restrict__ t2_g,
               const float* __restrict__ W1_g, const float* __restrict__ b1_g,
               const float* __restrict__ W2_g, const float* __restrict__ b2_g,
               const float* __restrict__ W3_g, const float* __restrict__ b3_g,
               float* __restrict__ out, int n)
{
    extern __shared__ char smc[];
    float* smf = (float*)smc;
    uint32_t sb;
    asm("{ .reg .u64 t; cvta.to.shared.u64 t, %1; cvt.u32.u64 %0, t; }" : "=r"(sb) : "l"(smc));

    const int tid  = threadIdx.x;
    const int lane = tid & 31;
    const int g    = lane >> 2;
    const int tig  = lane & 3;
    const int ng   = tid >> 5;           // warp 0..3 owns cols [ng*32, +32)
    const int m    = tid & 63;           // point in CTA
    const int kh   = tid >> 6;           // k half 0..1
    const int pbase = blockIdx.x * PPC;
    const int slot = pbase + m;
    const int myp = (slot < n) ? g_perm[slot] : -1;
    uint32_t* w1xps = (uint32_t*)(smc + OFF_W1XP);

    // ---- prologue: W1 (32KB) staged temporarily at smem base; cpre -> smem ----
    {
        float* w1tmp = (float*)smc;   // spans A0HI + start of CPRE; safe (barrier below)
        for (int i = tid; i < 64*HID; i += THREADS) w1tmp[i] = W1_g[i];
        if (tid < HID){
#pragma unroll
            for (int kk=0;kk<4;kk++) smf[FW1X + tid*4 + kk] = W1_g[(64+kk)*HID + tid];
        }
        __syncthreads();
        float acc[64];
#pragma unroll
        for (int i=0;i<64;i++) acc[i] = b1_g[kh*64 + i];
#pragma unroll 1
        for (int c0=0;c0<64;c0+=16){
            float cd[16];
#pragma unroll
            for (int u=0;u<16;u++)
                cd[u] = (myp>=0) ? code_g[(size_t)myp*64 + c0 + u] : 0.f;
#pragma unroll
            for (int u=0;u<16;u++){
                float cc = cd[u];
                const float* wr = w1tmp + (c0+u)*HID + kh*64;
#pragma unroll
                for (int i=0;i<64;i+=4){
                    float4 w = *(const float4*)(wr + i);
                    acc[i]   = fmaf(cc,w.x,acc[i]);
                    acc[i+1] = fmaf(cc,w.y,acc[i+1]);
                    acc[i+2] = fmaf(cc,w.z,acc[i+2]);
                    acc[i+3] = fmaf(cc,w.w,acc[i+3]);
                }
            }
        }
        __syncthreads();   // all w1tmp reads done before cpre overwrites the region
#pragma unroll
        for (int i=0;i<64;i++) smf[FCPRE + (kh*64+i)*64 + m] = acc[i];
        if (tid < 96){
            int j  = tid / 32;
            int kt = (tid >> 2) & 7;
            int tg = tid & 3;
            int k0 = kt*16 + tg*2;
            w1xps[((j*8+kt)*4+tg)*2 + 0] = packh(smf[FW1X + k0*4 + j],     smf[FW1X + (k0+1)*4 + j]);
            w1xps[((j*8+kt)*4+tg)*2 + 1] = packh(smf[FW1X + (k0+8)*4 + j], smf[FW1X + (k0+9)*4 + j]);
        }
        __syncthreads();
    }

    // ---- W2 fragments (fp16): this warp's 32 cols ----
    uint32_t bhh[4][8][2];
#pragma unroll
    for (int nt=0;nt<4;nt++)
#pragma unroll
    for (int kt=0;kt<8;kt++){
        int nn = ng*32 + nt*8 + g;
        int k0 = kt*16 + tig*2;
        float f0=W2_g[(size_t)k0*HID+nn],     f1=W2_g[(size_t)(k0+1)*HID+nn];
        float f2=W2_g[(size_t)(k0+8)*HID+nn], f3=W2_g[(size_t)(k0+9)*HID+nn];
        bhh[nt][kt][0]=packh(f0,f1); bhh[nt][kt][1]=packh(f2,f3);
    }
    float b2r[4][2], w3r[4][2][3];
#pragma unroll
    for (int nt=0;nt<4;nt++)
#pragma unroll
    for (int cj=0;cj<2;cj++){
        int nn = ng*32 + nt*8 + tig*2 + cj;
        b2r[nt][cj] = b2_g[nn];
        w3r[nt][cj][0]=W3_g[nn*3+0]; w3r[nt][cj][1]=W3_g[nn*3+1]; w3r[nt][cj][2]=W3_g[nn*3+2];
    }
    const float b3x=b3_g[0], b3y=b3_g[1], b3z=b3_g[2];

    float px=0.f,py=0.f,pz=0.f,tt=0.f,off=0.f;
    float D[9] = {1,0,0, 0,1,0, 0,0,1};
    if (myp>=0){
        px = pos_g[(size_t)myp*3+0];
        py = pos_g[(size_t)myp*3+1];
        pz = pos_g[(size_t)myp*3+2];
        tt = t1_g[myp];
        off = tt - t2_g[myp];
    }

    uint32_t g2p[4][4][2];

    // stage h (fp16 hi only) into A0
#define LAYER1_STAGE(X0,X1,X2,X3) do { \
        _Pragma("unroll") \
        for (int i2=0;i2<8;i2++){ \
            uint32_t hi4[4]; \
            _Pragma("unroll") \
            for (int u2=0;u2<4;u2++){ \
                int k0 = kh*64 + i2*8 + u2*2; \
                float a0 = smf[FCPRE + k0*64 + m]; \
                float a1 = smf[FCPRE + (k0+1)*64 + m]; \
                float4 w0 = *(const float4*)(smf + FW1X + k0*4); \
                float4 w1 = *(const float4*)(smf + FW1X + (k0+1)*4); \
                a0=fmaf((X0),w0.x,a0); a0=fmaf((X1),w0.y,a0); a0=fmaf((X2),w0.z,a0); a0=fmaf((X3),w0.w,a0); \
                a1=fmaf((X0),w1.x,a1); a1=fmaf((X1),w1.y,a1); a1=fmaf((X2),w1.z,a1); a1=fmaf((X3),w1.w,a1); \
                hi4[u2]=packh(ftanh(a0), ftanh(a1)); \
            } \
            *(uint4*)(smc + OFF_A0HI + m*APITCH + (kh*64+i2*8)*2) = make_uint4(hi4[0],hi4[1],hi4[2],hi4[3]); \
        } \
    } while(0)

    // in-place A0: h -> g1 = 1 - h^2 (fp16)
#define G1_CONVERT() do { \
        _Pragma("unroll") \
        for (int i2=0;i2<8;i2++){ \
            uint4 hu = *(const uint4*)(smc + OFF_A0HI + m*APITCH + (kh*64+i2*8)*2); \
            uint32_t hw[4]={hu.x,hu.y,hu.z,hu.w}; \
            uint32_t hi4[4]; \
            _Pragma("unroll") \
            for (int u2=0;u2<4;u2++){ \
                __half2 hh = *reinterpret_cast<__half2*>(&hw[u2]); \
                float h0 = __low2float(hh), h1 = __high2float(hh); \
                hi4[u2]=packh(fmaf(-h0,h0,1.f), fmaf(-h1,h1,1.f)); \
            } \
            *(uint4*)(smc + OFF_A0HI + m*APITCH + (kh*64+i2*8)*2) = make_uint4(hi4[0],hi4[1],hi4[2],hi4[3]); \
        } \
    } while(0)

#define SUMC(col) ({ float _s = 0.f; \
        _Pragma("unroll") \
        for (int gg=0;gg<4;gg++) _s += smf[FPSUM + gg*768 + m*12 + (col)]; \
        _s; })

#pragma unroll 1
    for (int s = 0; s < NSTEPS; s++){
        if (!__syncthreads_or(off != 0.0f)) break;

        // ---- fwd1 ----
        LAYER1_STAGE(px, py, pz, tt);
        __syncthreads();
        gemm_fwd<0>(smf, sb, lane, tig, g, ng, bhh, g2p, b2r, w3r);
        __syncthreads();
        float dt = copysignf(fminf(fabsf(off), DT_MAXF), off);
        float qx = fmaf(-0.5f*dt, SUMC(0)+b3x, px);
        float qy = fmaf(-0.5f*dt, SUMC(1)+b3y, py);
        float qz = fmaf(-0.5f*dt, SUMC(2)+b3z, pz);
        float qt = tt - 0.5f*dt;

        // ---- fwd2 (captures g2) ----
        LAYER1_STAGE(qx, qy, qz, qt);
        __syncthreads();
        gemm_fwd<1>(smf, sb, lane, tig, g, ng, bhh, g2p, b2r, w3r);
        __syncthreads();
        float vx = SUMC(0)+b3x, vy = SUMC(1)+b3y, vz = SUMC(2)+b3z;

        // ---- tangents: A0 h->g1 once, 3 single-direction fused GEMMs ----
        G1_CONVERT();
        __syncthreads();
        gemm_tan(smf, sb, 0, lane, tig, g, ng, bhh, w1xps, g2p, w3r);
        __syncthreads();
        gemm_tan(smf, sb, 1, lane, tig, g, ng, bhh, w1xps, g2p, w3r);
        gemm_tan(smf, sb, 2, lane, tig, g, ng, bhh, w1xps, g2p, w3r);
        __syncthreads();
        float jac[9];
#pragma unroll
        for (int q=0;q<9;q++) jac[q] = SUMC(q);

        float dr[9];
#pragma unroll
        for (int o=0;o<3;o++)
#pragma unroll
            for (int c=0;c<3;c++)
                dr[o*3+c] = jac[0+o]*D[0*3+c] + jac[3+o]*D[1*3+c] + jac[6+o]*D[2*3+c];
#pragma unroll
        for (int q=0;q<9;q++) D[q] = fmaf(-dt, dr[q], D[q]);
        px = fmaf(-dt, vx, px);
        py = fmaf(-dt, vy, py);
        pz = fmaf(-dt, vz, pz);
        tt -= dt; off -= dt;
    }

    if (kh == 0 && myp >= 0){
        out[(size_t)myp*3+0]=px; out[(size_t)myp*3+1]=py; out[(size_t)myp*3+2]=pz;
        float* od = out + (size_t)n*3 + (size_t)myp*9;
#pragma unroll
        for (int q=0;q<9;q++) od[q] = D[q];
    }
}

extern "C" void kernel_launch(void* const* d_in, const int* in_sizes, int n_in,
                              void* d_out, int out_size)
{
    const float* code = (const float*)d_in[0];
    const float* pos  = (const float*)d_in[1];
    const float* t1   = (const float*)d_in[2];
    const float* t2   = (const float*)d_in[3];
    const float* W1   = (const float*)d_in[4];
    const float* b1   = (const float*)d_in[5];
    const float* W2   = (const float*)d_in[6];
    const float* b2   = (const float*)d_in[7];
    const float* W3   = (const float*)d_in[8];
    const float* b3   = (const float*)d_in[9];
    const int n = in_sizes[2];
    const int nb = (n + 255)/256;

    k_hist<<<nb,256>>>(t1,t2,n);
    k_prefix<<<1,32>>>(nb);
    k_scatter<<<nb,256>>>(t1,t2,n);

    cudaFuncSetAttribute(velwarp_kernel,
                         cudaFuncAttributeMaxDynamicSharedMemorySize, SMEM_BYTES);
    velwarp_kernel<<<(n+PPC-1)/PPC, THREADS, SMEM_BYTES>>>(
        code, pos, t1, t2, W1, b1, W2, b2, W3, b3, (float*)d_out, n);
}

// round 16
// speedup vs baseline: 1.8598x; 1.1392x over previous
#include <cuda_runtime.h>
#include <cuda_fp16.h>
#include <cstdint>

#define HID 128
#define DT_MAXF 0.125f
#define NSTEPS 8
#define THREADS 128
#define PPC 64                  // points per CTA
#define MAXN (1<<18)
#define APITCH 272              // bytes per A row (128 fp16 + pad)

__device__ int g_parts[1024][16];
__device__ int g_cursor[16];
__device__ int g_perm[MAXN];

// ---- smem byte offsets (per-CTA 64KB -> 2 CTAs/SM) ----
#define OFF_A0HI 0              // 17408 (64 rows x 272B)
#define OFF_CPRE 17408          // 32768: cpre f32 [128 k][64 m]
#define OFF_PSUM 50176          // 12288: psum f32 [4 ng][64 m][12]
#define OFF_W1X  62464          // 2048 : f32 [k][4] = W1[64+q][k]
#define OFF_W1XP 64512          // 1024 : packed half2 table [3][8][4 tig][2]
#define SMEM_BYTES 65536

#define FCPRE (OFF_CPRE/4)
#define FPSUM (OFF_PSUM/4)
#define FW1X  (OFF_W1X/4)

__device__ __forceinline__ float ftanh(float x){
    float y;
    asm("tanh.approx.f32 %0, %1;" : "=f"(y) : "f"(x));
    return y;
}
__device__ __forceinline__ uint32_t packh(float a, float b){
    __half2 t = __floats2half2_rn(a, b);
    return *reinterpret_cast<uint32_t*>(&t);
}
__device__ __forceinline__ uint32_t hmul2u(uint32_t a, uint32_t b){
    __half2 r = __hmul2(*reinterpret_cast<__half2*>(&a), *reinterpret_cast<__half2*>(&b));
    return *reinterpret_cast<uint32_t*>(&r);
}
__device__ __forceinline__ void mma16816(float d[4], const uint32_t a[4], const uint32_t b[2]){
    asm volatile(
        "mma.sync.aligned.m16n8k16.row.col.f32.f16.f16.f32 "
        "{%0,%1,%2,%3}, {%4,%5,%6,%7}, {%8,%9}, {%0,%1,%2,%3};"
        : "+f"(d[0]), "+f"(d[1]), "+f"(d[2]), "+f"(d[3])
        : "r"(a[0]), "r"(a[1]), "r"(a[2]), "r"(a[3]), "r"(b[0]), "r"(b[1]));
}
__device__ __forceinline__ void ldmat4(uint32_t a[4], uint32_t addr){
    asm volatile("ldmatrix.sync.aligned.m8n8.x4.shared.b16 {%0,%1,%2,%3}, [%4];"
        : "=r"(a[0]), "=r"(a[1]), "=r"(a[2]), "=r"(a[3]) : "r"(addr) : "memory");
}

// Forward GEMM phase + fused epilogue. Warp tile: 64m x 32n (warp = ng).
// MODE 0: tanh(d+b2)*W3 -> psum cols 0..2 ; MODE 1: same + capture g2
template<int MODE>
__device__ __forceinline__ void gemm_fwd(float* smf, uint32_t sb,
        int lane, int tig, int g, int ng,
        const uint32_t (&bhh)[4][8][2], uint32_t (&g2p)[4][4][2],
        const float (&b2r)[4][2], const float (&w3r)[4][2][3])
{
    const uint32_t arow0 = sb + OFF_A0HI + (uint32_t)(lane & 15)*APITCH
                         + ((lane & 16) ? 16u : 0u);
#pragma unroll
    for (int mt = 0; mt < 4; mt++){
        uint32_t ab = arow0 + (uint32_t)(mt*16)*APITCH;
        float d[4][4];
#pragma unroll
        for (int nt=0;nt<4;nt++){ d[nt][0]=0.f; d[nt][1]=0.f; d[nt][2]=0.f; d[nt][3]=0.f; }
#pragma unroll
        for (int kt = 0; kt < 8; kt++){
            uint32_t ah[4];
            ldmat4(ah, ab + kt*32);
#pragma unroll
            for (int nt = 0; nt < 4; nt++)
                mma16816(d[nt], ah, bhh[nt][kt]);
        }
        float s[2][3] = {{0.f,0.f,0.f},{0.f,0.f,0.f}};
#pragma unroll
        for (int nt = 0; nt < 4; nt++){
#pragma unroll
            for (int rh = 0; rh < 2; rh++){
                float ng2[2];
#pragma unroll
                for (int cj = 0; cj < 2; cj++){
                    float hv = ftanh(d[nt][rh*2+cj] + b2r[nt][cj]);
                    ng2[cj] = fmaf(-hv, hv, 1.f);
                    s[rh][0] = fmaf(hv, w3r[nt][cj][0], s[rh][0]);
                    s[rh][1] = fmaf(hv, w3r[nt][cj][1], s[rh][1]);
                    s[rh][2] = fmaf(hv, w3r[nt][cj][2], s[rh][2]);
                }
                if (MODE == 1){
                    __half2 p = __floats2half2_rn(ng2[0], ng2[1]);
                    g2p[mt][nt][rh] = *reinterpret_cast<uint32_t*>(&p);
                }
            }
        }
#pragma unroll
        for (int rh = 0; rh < 2; rh++)
#pragma unroll
        for (int o = 0; o < 3; o++){
            float v = s[rh][o];
            v += __shfl_xor_sync(0xffffffffu, v, 1);
            v += __shfl_xor_sync(0xffffffffu, v, 2);
            s[rh][o] = v;
        }
        if (tig == 0){
            int row0 = mt*16 + g;
            float* p0 = smf + FPSUM + ng*768 + row0*12;
            p0[0]=s[0][0]; p0[1]=s[0][1]; p0[2]=s[0][2];
            float* p1 = p0 + 8*12;
            p1[0]=s[1][0]; p1[1]=s[1][1]; p1[2]=s[1][2];
        }
    }
}

// Tangent GEMM, one direction J: A = g1 (in A0), B_j = hmul2(W2_frag, w1xp_frag).
__device__ __forceinline__ void gemm_tan(float* smf, uint32_t sb, int J,
        int lane, int tig, int g, int ng,
        const uint32_t (&bhh)[4][8][2], const uint32_t* w1xps,
        const uint32_t (&g2p)[4][4][2], const float (&w3r)[4][2][3])
{
    const uint32_t arow0 = sb + OFF_A0HI + (uint32_t)(lane & 15)*APITCH
                         + ((lane & 16) ? 16u : 0u);
    uint32_t wjf[8][2];
#pragma unroll
    for (int kt=0;kt<8;kt++){
        const uint32_t* p = w1xps + ((J*8 + kt)*4 + tig)*2;
        wjf[kt][0] = p[0]; wjf[kt][1] = p[1];
    }
#pragma unroll
    for (int mt = 0; mt < 4; mt++){
        uint32_t ab = arow0 + (uint32_t)(mt*16)*APITCH;
        float d[4][4];
#pragma unroll
        for (int nt=0;nt<4;nt++){ d[nt][0]=0.f; d[nt][1]=0.f; d[nt][2]=0.f; d[nt][3]=0.f; }
#pragma unroll
        for (int kt = 0; kt < 8; kt++){
            uint32_t ah[4];
            ldmat4(ah, ab + kt*32);
#pragma unroll
            for (int nt = 0; nt < 4; nt++){
                uint32_t bb[2];
                bb[0] = hmul2u(bhh[nt][kt][0], wjf[kt][0]);
                bb[1] = hmul2u(bhh[nt][kt][1], wjf[kt][1]);
                mma16816(d[nt], ah, bb);
            }
        }
        float s[2][3] = {{0.f,0.f,0.f},{0.f,0.f,0.f}};
#pragma unroll
        for (int nt = 0; nt < 4; nt++)
#pragma unroll
        for (int rh = 0; rh < 2; rh++){
            uint32_t u = g2p[mt][nt][rh];
            __half2 hv2 = *reinterpret_cast<__half2*>(&u);
            float g2v[2] = { __low2float(hv2), __high2float(hv2) };
#pragma unroll
            for (int cj = 0; cj < 2; cj++){
                float use = d[nt][rh*2+cj] * g2v[cj];
                s[rh][0] = fmaf(use, w3r[nt][cj][0], s[rh][0]);
                s[rh][1] = fmaf(use, w3r[nt][cj][1], s[rh][1]);
                s[rh][2] = fmaf(use, w3r[nt][cj][2], s[rh][2]);
            }
        }
#pragma unroll
        for (int rh = 0; rh < 2; rh++)
#pragma unroll
        for (int o = 0; o < 3; o++){
            float v = s[rh][o];
            v += __shfl_xor_sync(0xffffffffu, v, 1);
            v += __shfl_xor_sync(0xffffffffu, v, 2);
            s[rh][o] = v;
        }
        if (tig == 0){
            int row0 = mt*16 + g;
            float* p0 = smf + FPSUM + ng*768 + row0*12;
            float* p1 = p0 + 8*12;
#pragma unroll
            for (int o = 0; o < 3; o++){
                p0[J*3+o] = s[0][o];
                p1[J*3+o] = s[1][o];
            }
        }
    }
}

// ---- bucketing: 3 kernels ----
__device__ __forceinline__ int steps_needed(float off){
    float a = fabsf(off);
    int k = (int)ceilf(a*8.0f);
    return k > NSTEPS ? NSTEPS : k;
}
__global__ void k_hist(const float* t1, const float* t2, int n){
    __shared__ int lh[16];
    if (threadIdx.x < 16) lh[threadIdx.x] = 0;
    __syncthreads();
    int i = blockIdx.x*blockDim.x + threadIdx.x;
    if (i < n) atomicAdd(&lh[steps_needed(t1[i]-t2[i])], 1);
    __syncthreads();
    if (threadIdx.x < 16) g_parts[blockIdx.x][threadIdx.x] = lh[threadIdx.x];
}
__global__ void k_prefix(int nb){
    __shared__ int tot[16];
    int b = threadIdx.x;
    if (b < 16){
        int s = 0;
        for (int blk = 0; blk < nb; blk++) s += g_parts[blk][b];
        tot[b] = s;
    }
    __syncthreads();
    if (threadIdx.x == 0){
        int s = 0;
#pragma unroll
        for (int q = 0; q <= NSTEPS; q++){ g_cursor[q] = s; s += tot[q]; }
    }
}
__global__ void k_scatter(const float* t1, const float* t2, int n){
    __shared__ int lh[16], lb[16];
    if (threadIdx.x < 16) lh[threadIdx.x] = 0;
    __syncthreads();
    int i = blockIdx.x*blockDim.x + threadIdx.x;
    int k = 0, loc = 0; bool v = (i < n);
    if (v){ k = steps_needed(t1[i]-t2[i]); loc = atomicAdd(&lh[k], 1); }
    __syncthreads();
    if (threadIdx.x < 16 && lh[threadIdx.x])
        lb[threadIdx.x] = atomicAdd(&g_cursor[threadIdx.x], lh[threadIdx.x]);
    __syncthreads();
    if (v) g_perm[lb[k]+loc] = i;
}

__global__ void __launch_bounds__(THREADS, 2)
velwarp_kernel(const float* __restrict__ code_g, const float* __restrict__ pos_g,
               const float* __restrict__ t1_g, const float* __restrict__ t2_g,
               const float* __restrict__ W1_g, const float* __restrict__ b1_g,
               const float* __restrict__ W2_g, const float* __restrict__ b2_g,
               const float* __restrict__ W3_g, const float* __restrict__ b3_g,
               float* __restrict__ out, int n)
{
    extern __shared__ char smc[];
    __shared__ int s_smax;
    float* smf = (float*)smc;
    uint32_t sb;
    asm("{ .reg .u64 t; cvta.to.shared.u64 t, %1; cvt.u32.u64 %0, t; }" : "=r"(sb) : "l"(smc));

    const int tid  = threadIdx.x;
    const int lane = tid & 31;
    const int g    = lane >> 2;
    const int tig  = lane & 3;
    const int ng   = tid >> 5;           // warp 0..3 owns cols [ng*32, +32)
    const int m    = tid & 63;           // point in CTA
    const int kh   = tid >> 6;           // k half 0..1
    const int pbase = blockIdx.x * PPC;
    const int slot = pbase + m;
    const int myp = (slot < n) ? g_perm[slot] : -1;
    uint32_t* w1xps = (uint32_t*)(smc + OFF_W1XP);

    if (tid == 0) s_smax = 0;

    // ---- prologue: W1 (32KB) staged temporarily at smem base; cpre -> smem ----
    {
        float* w1tmp = (float*)smc;
        for (int i = tid; i < 64*HID; i += THREADS) w1tmp[i] = W1_g[i];
        if (tid < HID){
#pragma unroll
            for (int kk=0;kk<4;kk++) smf[FW1X + tid*4 + kk] = W1_g[(64+kk)*HID + tid];
        }
        __syncthreads();
        float acc[64];
#pragma unroll
        for (int i=0;i<64;i++) acc[i] = b1_g[kh*64 + i];
#pragma unroll 1
        for (int c0=0;c0<64;c0+=16){
            float cd[16];
#pragma unroll
            for (int u=0;u<16;u++)
                cd[u] = (myp>=0) ? code_g[(size_t)myp*64 + c0 + u] : 0.f;
#pragma unroll
            for (int u=0;u<16;u++){
                float cc = cd[u];
                const float* wr = w1tmp + (c0+u)*HID + kh*64;
#pragma unroll
                for (int i=0;i<64;i+=4){
                    float4 w = *(const float4*)(wr + i);
                    acc[i]   = fmaf(cc,w.x,acc[i]);
                    acc[i+1] = fmaf(cc,w.y,acc[i+1]);
                    acc[i+2] = fmaf(cc,w.z,acc[i+2]);
                    acc[i+3] = fmaf(cc,w.w,acc[i+3]);
                }
            }
        }
        __syncthreads();
#pragma unroll
        for (int i=0;i<64;i++) smf[FCPRE + (kh*64+i)*64 + m] = acc[i];
        if (tid < 96){
            int j  = tid / 32;
            int kt = (tid >> 2) & 7;
            int tg = tid & 3;
            int k0 = kt*16 + tg*2;
            w1xps[((j*8+kt)*4+tg)*2 + 0] = packh(smf[FW1X + k0*4 + j],     smf[FW1X + (k0+1)*4 + j]);
            w1xps[((j*8+kt)*4+tg)*2 + 1] = packh(smf[FW1X + (k0+8)*4 + j], smf[FW1X + (k0+9)*4 + j]);
        }
    }

    // ---- W2 fragments (fp16): this warp's 32 cols ----
    uint32_t bhh[4][8][2];
#pragma unroll
    for (int nt=0;nt<4;nt++)
#pragma unroll
    for (int kt=0;kt<8;kt++){
        int nn = ng*32 + nt*8 + g;
        int k0 = kt*16 + tig*2;
        float f0=W2_g[(size_t)k0*HID+nn],     f1=W2_g[(size_t)(k0+1)*HID+nn];
        float f2=W2_g[(size_t)(k0+8)*HID+nn], f3=W2_g[(size_t)(k0+9)*HID+nn];
        bhh[nt][kt][0]=packh(f0,f1); bhh[nt][kt][1]=packh(f2,f3);
    }
    float b2r[4][2], w3r[4][2][3];
#pragma unroll
    for (int nt=0;nt<4;nt++)
#pragma unroll
    for (int cj=0;cj<2;cj++){
        int nn = ng*32 + nt*8 + tig*2 + cj;
        b2r[nt][cj] = b2_g[nn];
        w3r[nt][cj][0]=W3_g[nn*3+0]; w3r[nt][cj][1]=W3_g[nn*3+1]; w3r[nt][cj][2]=W3_g[nn*3+2];
    }
    const float b3x=b3_g[0], b3y=b3_g[1], b3z=b3_g[2];

    float px=0.f,py=0.f,pz=0.f,tt=0.f,off=0.f;
    float D[9] = {1,0,0, 0,1,0, 0,0,1};
    if (myp>=0){
        px = pos_g[(size_t)myp*3+0];
        py = pos_g[(size_t)myp*3+1];
        pz = pos_g[(size_t)myp*3+2];
        tt = t1_g[myp];
        off = tt - t2_g[myp];
    }
    // CTA-uniform step count (bucketing makes this tight; extras are exact no-ops)
    if (kh == 0 && off != 0.0f) atomicMax(&s_smax, steps_needed(off));
    __syncthreads();
    const int smax = s_smax;

    uint32_t g2p[4][4][2];

#define LAYER1_STAGE(X0,X1,X2,X3) do { \
        _Pragma("unroll") \
        for (int i2=0;i2<8;i2++){ \
            uint32_t hi4[4]; \
            _Pragma("unroll") \
            for (int u2=0;u2<4;u2++){ \
                int k0 = kh*64 + i2*8 + u2*2; \
                float a0 = smf[FCPRE + k0*64 + m]; \
                float a1 = smf[FCPRE + (k0+1)*64 + m]; \
                float4 w0 = *(const float4*)(smf + FW1X + k0*4); \
                float4 w1 = *(const float4*)(smf + FW1X + (k0+1)*4); \
                a0=fmaf((X0),w0.x,a0); a0=fmaf((X1),w0.y,a0); a0=fmaf((X2),w0.z,a0); a0=fmaf((X3),w0.w,a0); \
                a1=fmaf((X0),w1.x,a1); a1=fmaf((X1),w1.y,a1); a1=fmaf((X2),w1.z,a1); a1=fmaf((X3),w1.w,a1); \
                hi4[u2]=packh(ftanh(a0), ftanh(a1)); \
            } \
            *(uint4*)(smc + OFF_A0HI + m*APITCH + (kh*64+i2*8)*2) = make_uint4(hi4[0],hi4[1],hi4[2],hi4[3]); \
        } \
    } while(0)

#define G1_CONVERT() do { \
        _Pragma("unroll") \
        for (int i2=0;i2<8;i2++){ \
            uint4 hu = *(const uint4*)(smc + OFF_A0HI + m*APITCH + (kh*64+i2*8)*2); \
            uint32_t hw[4]={hu.x,hu.y,hu.z,hu.w}; \
            uint32_t hi4[4]; \
            _Pragma("unroll") \
            for (int u2=0;u2<4;u2++){ \
                __half2 hh = *reinterpret_cast<__half2*>(&hw[u2]); \
                float h0 = __low2float(hh), h1 = __high2float(hh); \
                hi4[u2]=packh(fmaf(-h0,h0,1.f), fmaf(-h1,h1,1.f)); \
            } \
            *(uint4*)(smc + OFF_A0HI + m*APITCH + (kh*64+i2*8)*2) = make_uint4(hi4[0],hi4[1],hi4[2],hi4[3]); \
        } \
    } while(0)

#define SUMC(col) ({ float _s = 0.f; \
        _Pragma("unroll") \
        for (int gg=0;gg<4;gg++) _s += smf[FPSUM + gg*768 + m*12 + (col)]; \
        _s; })

#pragma unroll 1
    for (int s = 0; s < smax; s++){
        // ---- fwd1 ----
        LAYER1_STAGE(px, py, pz, tt);
        __syncthreads();
        gemm_fwd<0>(smf, sb, lane, tig, g, ng, bhh, g2p, b2r, w3r);
        __syncthreads();
        float dt = copysignf(fminf(fabsf(off), DT_MAXF), off);
        float qx = fmaf(-0.5f*dt, SUMC(0)+b3x, px);
        float qy = fmaf(-0.5f*dt, SUMC(1)+b3y, py);
        float qz = fmaf(-0.5f*dt, SUMC(2)+b3z, pz);
        float qt = tt - 0.5f*dt;

        // ---- fwd2 (captures g2) ----
        LAYER1_STAGE(qx, qy, qz, qt);
        __syncthreads();
        gemm_fwd<1>(smf, sb, lane, tig, g, ng, bhh, g2p, b2r, w3r);
        __syncthreads();
        float vx = SUMC(0)+b3x, vy = SUMC(1)+b3y, vz = SUMC(2)+b3z;

        // ---- tangents ----
        G1_CONVERT();
        __syncthreads();
        gemm_tan(smf, sb, 0, lane, tig, g, ng, bhh, w1xps, g2p, w3r);
        __syncthreads();
        gemm_tan(smf, sb, 1, lane, tig, g, ng, bhh, w1xps, g2p, w3r);
        gemm_tan(smf, sb, 2, lane, tig, g, ng, bhh, w1xps, g2p, w3r);
        __syncthreads();
        float jac[9];
#pragma unroll
        for (int q=0;q<9;q++) jac[q] = SUMC(q);

        float dr[9];
#pragma unroll
        for (int o=0;o<3;o++)
#pragma unroll
            for (int c=0;c<3;c++)
                dr[o*3+c] = jac[0+o]*D[0*3+c] + jac[3+o]*D[1*3+c] + jac[6+o]*D[2*3+c];
#pragma unroll
        for (int q=0;q<9;q++) D[q] = fmaf(-dt, dr[q], D[q]);
        px = fmaf(-dt, vx, px);
        py = fmaf(-dt, vy, py);
        pz = fmaf(-dt, vz, pz);
        tt -= dt; off -= dt;
    }

    if (kh == 0 && myp >= 0){
        out[(size_t)myp*3+0]=px; out[(size_t)myp*3+1]=py; out[(size_t)myp*3+2]=pz;
        float* od = out + (size_t)n*3 + (size_t)myp*9;
#pragma unroll
        for (int q=0;q<9;q++) od[q] = D[q];
    }
}

extern "C" void kernel_launch(void* const* d_in, const int* in_sizes, int n_in,
                              void* d_out, int out_size)
{
    const float* code = (const float*)d_in[0];
    const float* pos  = (const float*)d_in[1];
    const float* t1   = (const float*)d_in[2];
    const float* t2   = (const float*)d_in[3];
    const float* W1   = (const float*)d_in[4];
    const float* b1   = (const float*)d_in[5];
    const float* W2   = (const float*)d_in[6];
    const float* b2   = (const float*)d_in[7];
    const float* W3   = (const float*)d_in[8];
    const float* b3   = (const float*)d_in[9];
    const int n = in_sizes[2];
    const int nb = (n + 255)/256;

    k_hist<<<nb,256>>>(t1,t2,n);
    k_prefix<<<1,32>>>(nb);
    k_scatter<<<nb,256>>>(t1,t2,n);

    cudaFuncSetAttribute(velwarp_kernel,
                         cudaFuncAttributeMaxDynamicSharedMemorySize, SMEM_BYTES);
    velwarp_kernel<<<(n+PPC-1)/PPC, THREADS, SMEM_BYTES>>>(
        code, pos, t1, t2, W1, b1, W2, b2, W3, b3, (float*)d_out, n);
}

// round 17
// speedup vs baseline: 1.9947x; 1.0725x over previous
#include <cuda_runtime.h>
#include <cuda_fp16.h>
#include <cstdint>

#define HID 128
#define DT_MAXF 0.125f
#define NSTEPS 8
#define THREADS 128
#define PPC 64                  // points per CTA
#define MAXN (1<<18)
#define APITCH 272              // bytes per A row (128 fp16 + pad)

__device__ int g_parts[1024][16];
__device__ int g_cursor[16];
__device__ int g_perm[MAXN];

// ---- smem byte offsets (per-CTA ~97KB -> 2 CTAs/SM) ----
#define OFF_A    0              // 52224: A fp16 [192 rows][136] (rows 64j+m = g1*w1x_j)
#define OFF_CPRE 52224          // 32768: cpre f32 [128 k][64 m]
#define OFF_PSUM 84992          // 12288: psum f32 [4 ng][64 m][12] (0-2 vel, 3-11 jac)
#define OFF_W1X  97280          // 2048 : f32 [k][4] = W1[64+q][k]
#define SMEM_BYTES 99328

#define FCPRE (OFF_CPRE/4)
#define FPSUM (OFF_PSUM/4)
#define FW1X  (OFF_W1X/4)

__device__ __forceinline__ float ftanh(float x){
    float y;
    asm("tanh.approx.f32 %0, %1;" : "=f"(y) : "f"(x));
    return y;
}
__device__ __forceinline__ uint32_t packh(float a, float b){
    __half2 t = __floats2half2_rn(a, b);
    return *reinterpret_cast<uint32_t*>(&t);
}
__device__ __forceinline__ void mma16816(float d[4], const uint32_t a[4], const uint32_t b[2]){
    asm volatile(
        "mma.sync.aligned.m16n8k16.row.col.f32.f16.f16.f32 "
        "{%0,%1,%2,%3}, {%4,%5,%6,%7}, {%8,%9}, {%0,%1,%2,%3};"
        : "+f"(d[0]), "+f"(d[1]), "+f"(d[2]), "+f"(d[3])
        : "r"(a[0]), "r"(a[1]), "r"(a[2]), "r"(a[3]), "r"(b[0]), "r"(b[1]));
}
__device__ __forceinline__ void ldmat4(uint32_t a[4], uint32_t addr){
    asm volatile("ldmatrix.sync.aligned.m8n8.x4.shared.b16 {%0,%1,%2,%3}, [%4];"
        : "=r"(a[0]), "=r"(a[1]), "=r"(a[2]), "=r"(a[3]) : "r"(addr) : "memory");
}

// Forward GEMM phase + fused epilogue over A rows [0,64). Warp tile 64m x 32n.
// MODE 0: tanh(d+b2)*W3 -> psum cols 0..2 ; MODE 1: same + capture g2
template<int MODE>
__device__ __forceinline__ void gemm_fwd(float* smf, uint32_t sb,
        int lane, int tig, int g, int ng,
        const uint32_t (&bhh)[4][8][2], uint32_t (&g2p)[4][4][2],
        const float (&b2r)[4][2], const float (&w3r)[4][2][3])
{
    const uint32_t arow0 = sb + OFF_A + (uint32_t)(lane & 15)*APITCH
                         + ((lane & 16) ? 16u : 0u);
#pragma unroll
    for (int mt = 0; mt < 4; mt++){
        uint32_t ab = arow0 + (uint32_t)(mt*16)*APITCH;
        float d[4][4];
#pragma unroll
        for (int nt=0;nt<4;nt++){ d[nt][0]=0.f; d[nt][1]=0.f; d[nt][2]=0.f; d[nt][3]=0.f; }
#pragma unroll
        for (int kt = 0; kt < 8; kt++){
            uint32_t ah[4];
            ldmat4(ah, ab + kt*32);
#pragma unroll
            for (int nt = 0; nt < 4; nt++)
                mma16816(d[nt], ah, bhh[nt][kt]);
        }
        float s[2][3] = {{0.f,0.f,0.f},{0.f,0.f,0.f}};
#pragma unroll
        for (int nt = 0; nt < 4; nt++){
#pragma unroll
            for (int rh = 0; rh < 2; rh++){
                float ng2[2];
#pragma unroll
                for (int cj = 0; cj < 2; cj++){
                    float hv = ftanh(d[nt][rh*2+cj] + b2r[nt][cj]);
                    ng2[cj] = fmaf(-hv, hv, 1.f);
                    s[rh][0] = fmaf(hv, w3r[nt][cj][0], s[rh][0]);
                    s[rh][1] = fmaf(hv, w3r[nt][cj][1], s[rh][1]);
                    s[rh][2] = fmaf(hv, w3r[nt][cj][2], s[rh][2]);
                }
                if (MODE == 1){
                    __half2 p = __floats2half2_rn(ng2[0], ng2[1]);
                    g2p[mt][nt][rh] = *reinterpret_cast<uint32_t*>(&p);
                }
            }
        }
#pragma unroll
        for (int rh = 0; rh < 2; rh++)
#pragma unroll
        for (int o = 0; o < 3; o++){
            float v = s[rh][o];
            v += __shfl_xor_sync(0xffffffffu, v, 1);
            v += __shfl_xor_sync(0xffffffffu, v, 2);
            s[rh][o] = v;
        }
        if (tig == 0){
            int row0 = mt*16 + g;
            float* p0 = smf + FPSUM + ng*768 + row0*12;
            p0[0]=s[0][0]; p0[1]=s[0][1]; p0[2]=s[0][2];
            float* p1 = p0 + 8*12;
            p1[0]=s[1][0]; p1[1]=s[1][1]; p1[2]=s[1][2];
        }
    }
}

// Fused tangent GEMM: ONE phase over A rows [0,192) (row 64j+m = g1[m]*w1x_j),
// plain B = W2 fragments. Epilogue (d*g2)*W3 -> psum cols 3+j*3 .. +2.
__device__ __forceinline__ void gemm_tan(float* smf, uint32_t sb,
        int lane, int tig, int g, int ng,
        const uint32_t (&bhh)[4][8][2],
        const uint32_t (&g2p)[4][4][2], const float (&w3r)[4][2][3])
{
    const uint32_t arow0 = sb + OFF_A + (uint32_t)(lane & 15)*APITCH
                         + ((lane & 16) ? 16u : 0u);
#pragma unroll
    for (int mt = 0; mt < 12; mt++){
        uint32_t ab = arow0 + (uint32_t)(mt*16)*APITCH;
        float d[4][4];
#pragma unroll
        for (int nt=0;nt<4;nt++){ d[nt][0]=0.f; d[nt][1]=0.f; d[nt][2]=0.f; d[nt][3]=0.f; }
#pragma unroll
        for (int kt = 0; kt < 8; kt++){
            uint32_t ah[4];
            ldmat4(ah, ab + kt*32);
#pragma unroll
            for (int nt = 0; nt < 4; nt++)
                mma16816(d[nt], ah, bhh[nt][kt]);
        }
        const int mtl = mt & 3;         // m-tile within 64-row block
        const int j   = mt >> 2;        // tangent direction
        float s[2][3] = {{0.f,0.f,0.f},{0.f,0.f,0.f}};
#pragma unroll
        for (int nt = 0; nt < 4; nt++)
#pragma unroll
        for (int rh = 0; rh < 2; rh++){
            uint32_t u = g2p[mtl][nt][rh];
            __half2 hv2 = *reinterpret_cast<__half2*>(&u);
            float g2v[2] = { __low2float(hv2), __high2float(hv2) };
#pragma unroll
            for (int cj = 0; cj < 2; cj++){
                float use = d[nt][rh*2+cj] * g2v[cj];
                s[rh][0] = fmaf(use, w3r[nt][cj][0], s[rh][0]);
                s[rh][1] = fmaf(use, w3r[nt][cj][1], s[rh][1]);
                s[rh][2] = fmaf(use, w3r[nt][cj][2], s[rh][2]);
            }
        }
#pragma unroll
        for (int rh = 0; rh < 2; rh++)
#pragma unroll
        for (int o = 0; o < 3; o++){
            float v = s[rh][o];
            v += __shfl_xor_sync(0xffffffffu, v, 1);
            v += __shfl_xor_sync(0xffffffffu, v, 2);
            s[rh][o] = v;
        }
        if (tig == 0){
            int pm = mtl*16 + g;        // point row
            float* p0 = smf + FPSUM + ng*768 + pm*12 + 3 + j*3;
            float* p1 = p0 + 8*12;
#pragma unroll
            for (int o = 0; o < 3; o++){ p0[o] = s[0][o]; p1[o] = s[1][o]; }
        }
    }
}

// ---- bucketing: 3 kernels ----
__device__ __forceinline__ int steps_needed(float off){
    float a = fabsf(off);
    int k = (int)ceilf(a*8.0f);
    return k > NSTEPS ? NSTEPS : k;
}
__global__ void k_hist(const float* t1, const float* t2, int n){
    __shared__ int lh[16];
    if (threadIdx.x < 16) lh[threadIdx.x] = 0;
    __syncthreads();
    int i = blockIdx.x*blockDim.x + threadIdx.x;
    if (i < n) atomicAdd(&lh[steps_needed(t1[i]-t2[i])], 1);
    __syncthreads();
    if (threadIdx.x < 16) g_parts[blockIdx.x][threadIdx.x] = lh[threadIdx.x];
}
__global__ void k_prefix(int nb){
    __shared__ int tot[16];
    int b = threadIdx.x;
    if (b < 16){
        int s = 0;
        for (int blk = 0; blk < nb; blk++) s += g_parts[blk][b];
        tot[b] = s;
    }
    __syncthreads();
    if (threadIdx.x == 0){
        int s = 0;
#pragma unroll
        for (int q = 0; q <= NSTEPS; q++){ g_cursor[q] = s; s += tot[q]; }
    }
}
__global__ void k_scatter(const float* t1, const float* t2, int n){
    __shared__ int lh[16], lb[16];
    if (threadIdx.x < 16) lh[threadIdx.x] = 0;
    __syncthreads();
    int i = blockIdx.x*blockDim.x + threadIdx.x;
    int k = 0, loc = 0; bool v = (i < n);
    if (v){ k = steps_needed(t1[i]-t2[i]); loc = atomicAdd(&lh[k], 1); }
    __syncthreads();
    if (threadIdx.x < 16 && lh[threadIdx.x])
        lb[threadIdx.x] = atomicAdd(&g_cursor[threadIdx.x], lh[threadIdx.x]);
    __syncthreads();
    if (v) g_perm[lb[k]+loc] = i;
}

__global__ void __launch_bounds__(THREADS, 2)
velwarp_kernel(const float* __restrict__ code_g, const float* __restrict__ pos_g,
               const float* __restrict__ t1_g, const float* __restrict__ t2_g,
               const float* __restrict__ W1_g, const float* __restrict__ b1_g,
               const float* __restrict__ W2_g, const float* __restrict__ b2_g,
               const float* __restrict__ W3_g, const float* __restrict__ b3_g,
               float* __restrict__ out, int n)
{
    extern __shared__ char smc[];
    __shared__ int s_smax;
    float* smf = (float*)smc;
    uint32_t sb;
    asm("{ .reg .u64 t; cvta.to.shared.u64 t, %1; cvt.u32.u64 %0, t; }" : "=r"(sb) : "l"(smc));

    const int tid  = threadIdx.x;
    const int lane = tid & 31;
    const int g    = lane >> 2;
    const int tig  = lane & 3;
    const int ng   = tid >> 5;           // warp 0..3 owns cols [ng*32, +32)
    const int m    = tid & 63;           // point in CTA
    const int kh   = tid >> 6;           // k half 0..1
    const int pbase = blockIdx.x * PPC;
    const int slot = pbase + m;
    const int myp = (slot < n) ? g_perm[slot] : -1;

    if (tid == 0) s_smax = 0;

    // ---- prologue: W1 (32KB) staged temporarily at smem base; cpre -> smem ----
    {
        float* w1tmp = (float*)smc;
        for (int i = tid; i < 64*HID; i += THREADS) w1tmp[i] = W1_g[i];
        if (tid < HID){
#pragma unroll
            for (int kk=0;kk<4;kk++) smf[FW1X + tid*4 + kk] = W1_g[(64+kk)*HID + tid];
        }
        __syncthreads();
        float acc[64];
#pragma unroll
        for (int i=0;i<64;i++) acc[i] = b1_g[kh*64 + i];
#pragma unroll 1
        for (int c0=0;c0<64;c0+=16){
            float cd[16];
#pragma unroll
            for (int u=0;u<16;u++)
                cd[u] = (myp>=0) ? code_g[(size_t)myp*64 + c0 + u] : 0.f;
#pragma unroll
            for (int u=0;u<16;u++){
                float cc = cd[u];
                const float* wr = w1tmp + (c0+u)*HID + kh*64;
#pragma unroll
                for (int i=0;i<64;i+=4){
                    float4 w = *(const float4*)(wr + i);
                    acc[i]   = fmaf(cc,w.x,acc[i]);
                    acc[i+1] = fmaf(cc,w.y,acc[i+1]);
                    acc[i+2] = fmaf(cc,w.z,acc[i+2]);
                    acc[i+3] = fmaf(cc,w.w,acc[i+3]);
                }
            }
        }
        __syncthreads();
#pragma unroll
        for (int i=0;i<64;i++) smf[FCPRE + (kh*64+i)*64 + m] = acc[i];
    }

    // ---- W2 fragments (fp16): this warp's 32 cols ----
    uint32_t bhh[4][8][2];
#pragma unroll
    for (int nt=0;nt<4;nt++)
#pragma unroll
    for (int kt=0;kt<8;kt++){
        int nn = ng*32 + nt*8 + g;
        int k0 = kt*16 + tig*2;
        float f0=W2_g[(size_t)k0*HID+nn],     f1=W2_g[(size_t)(k0+1)*HID+nn];
        float f2=W2_g[(size_t)(k0+8)*HID+nn], f3=W2_g[(size_t)(k0+9)*HID+nn];
        bhh[nt][kt][0]=packh(f0,f1); bhh[nt][kt][1]=packh(f2,f3);
    }
    float b2r[4][2], w3r[4][2][3];
#pragma unroll
    for (int nt=0;nt<4;nt++)
#pragma unroll
    for (int cj=0;cj<2;cj++){
        int nn = ng*32 + nt*8 + tig*2 + cj;
        b2r[nt][cj] = b2_g[nn];
        w3r[nt][cj][0]=W3_g[nn*3+0]; w3r[nt][cj][1]=W3_g[nn*3+1]; w3r[nt][cj][2]=W3_g[nn*3+2];
    }
    const float b3x=b3_g[0], b3y=b3_g[1], b3z=b3_g[2];

    float px=0.f,py=0.f,pz=0.f,tt=0.f,off=0.f;
    float D[9] = {1,0,0, 0,1,0, 0,0,1};
    if (myp>=0){
        px = pos_g[(size_t)myp*3+0];
        py = pos_g[(size_t)myp*3+1];
        pz = pos_g[(size_t)myp*3+2];
        tt = t1_g[myp];
        off = tt - t2_g[myp];
    }
    if (kh == 0 && off != 0.0f) atomicMax(&s_smax, steps_needed(off));
    __syncthreads();
    const int smax = s_smax;

    uint32_t g2p[4][4][2];

#define LAYER1_STAGE(X0,X1,X2,X3) do { \
        _Pragma("unroll") \
        for (int i2=0;i2<8;i2++){ \
            uint32_t hi4[4]; \
            _Pragma("unroll") \
            for (int u2=0;u2<4;u2++){ \
                int k0 = kh*64 + i2*8 + u2*2; \
                float a0 = smf[FCPRE + k0*64 + m]; \
                float a1 = smf[FCPRE + (k0+1)*64 + m]; \
                float4 w0 = *(const float4*)(smf + FW1X + k0*4); \
                float4 w1 = *(const float4*)(smf + FW1X + (k0+1)*4); \
                a0=fmaf((X0),w0.x,a0); a0=fmaf((X1),w0.y,a0); a0=fmaf((X2),w0.z,a0); a0=fmaf((X3),w0.w,a0); \
                a1=fmaf((X0),w1.x,a1); a1=fmaf((X1),w1.y,a1); a1=fmaf((X2),w1.z,a1); a1=fmaf((X3),w1.w,a1); \
                hi4[u2]=packh(ftanh(a0), ftanh(a1)); \
            } \
            *(uint4*)(smc + OFF_A + m*APITCH + (kh*64+i2*8)*2) = make_uint4(hi4[0],hi4[1],hi4[2],hi4[3]); \
        } \
    } while(0)

    // read h (rows 0..63), write A_j rows 64j+m: g1*w1x_j, j=0,1,2 (j=0 in place)
#define G1TAN_STAGE() do { \
        _Pragma("unroll") \
        for (int i2=0;i2<8;i2++){ \
            uint4 hu = *(const uint4*)(smc + OFF_A + m*APITCH + (kh*64+i2*8)*2); \
            uint32_t hw[4]={hu.x,hu.y,hu.z,hu.w}; \
            uint32_t o0[4], o1[4], o2[4]; \
            _Pragma("unroll") \
            for (int u2=0;u2<4;u2++){ \
                int k0 = kh*64 + i2*8 + u2*2; \
                __half2 hh = *reinterpret_cast<__half2*>(&hw[u2]); \
                float h0 = __low2float(hh), h1 = __high2float(hh); \
                float g0 = fmaf(-h0,h0,1.f), g1v = fmaf(-h1,h1,1.f); \
                float4 wa = *(const float4*)(smf + FW1X + k0*4); \
                float4 wb = *(const float4*)(smf + FW1X + (k0+1)*4); \
                o0[u2]=packh(g0*wa.x, g1v*wb.x); \
                o1[u2]=packh(g0*wa.y, g1v*wb.y); \
                o2[u2]=packh(g0*wa.z, g1v*wb.z); \
            } \
            *(uint4*)(smc + OFF_A + m*APITCH + (kh*64+i2*8)*2)            = make_uint4(o0[0],o0[1],o0[2],o0[3]); \
            *(uint4*)(smc + OFF_A + (64+m)*APITCH + (kh*64+i2*8)*2)       = make_uint4(o1[0],o1[1],o1[2],o1[3]); \
            *(uint4*)(smc + OFF_A + (128+m)*APITCH + (kh*64+i2*8)*2)      = make_uint4(o2[0],o2[1],o2[2],o2[3]); \
        } \
    } while(0)

#define SUMC(col) ({ float _s = 0.f; \
        _Pragma("unroll") \
        for (int gg=0;gg<4;gg++) _s += smf[FPSUM + gg*768 + m*12 + (col)]; \
        _s; })

#pragma unroll 1
    for (int s = 0; s < smax; s++){
        // ---- fwd1 ----
        LAYER1_STAGE(px, py, pz, tt);
        __syncthreads();
        gemm_fwd<0>(smf, sb, lane, tig, g, ng, bhh, g2p, b2r, w3r);
        __syncthreads();
        float dt = copysignf(fminf(fabsf(off), DT_MAXF), off);
        float qx = fmaf(-0.5f*dt, SUMC(0)+b3x, px);
        float qy = fmaf(-0.5f*dt, SUMC(1)+b3y, py);
        float qz = fmaf(-0.5f*dt, SUMC(2)+b3z, pz);
        float qt = tt - 0.5f*dt;

        // ---- fwd2 (captures g2) ----
        LAYER1_STAGE(qx, qy, qz, qt);
        __syncthreads();
        gemm_fwd<1>(smf, sb, lane, tig, g, ng, bhh, g2p, b2r, w3r);
        __syncthreads();
        float vx = SUMC(0)+b3x, vy = SUMC(1)+b3y, vz = SUMC(2)+b3z;

        // ---- tangents: stage all 3 A_j tiles, one 192-row GEMM phase ----
        G1TAN_STAGE();
        __syncthreads();
        gemm_tan(smf, sb, lane, tig, g, ng, bhh, g2p, w3r);
        __syncthreads();
        float jac[9];
#pragma unroll
        for (int q=0;q<9;q++) jac[q] = SUMC(3+q);

        float dr[9];
#pragma unroll
        for (int o=0;o<3;o++)
#pragma unroll
            for (int c=0;c<3;c++)
                dr[o*3+c] = jac[0+o]*D[0*3+c] + jac[3+o]*D[1*3+c] + jac[6+o]*D[2*3+c];
#pragma unroll
        for (int q=0;q<9;q++) D[q] = fmaf(-dt, dr[q], D[q]);
        px = fmaf(-dt, vx, px);
        py = fmaf(-dt, vy, py);
        pz = fmaf(-dt, vz, pz);
        tt -= dt; off -= dt;
    }

    if (kh == 0 && myp >= 0){
        out[(size_t)myp*3+0]=px; out[(size_t)myp*3+1]=py; out[(size_t)myp*3+2]=pz;
        float* od = out + (size_t)n*3 + (size_t)myp*9;
#pragma unroll
        for (int q=0;q<9;q++) od[q] = D[q];
    }
}

extern "C" void kernel_launch(void* const* d_in, const int* in_sizes, int n_in,
                              void* d_out, int out_size)
{
    const float* code = (const float*)d_in[0];
    const float* pos  = (const float*)d_in[1];
    const float* t1   = (const float*)d_in[2];
    const float* t2   = (const float*)d_in[3];
    const float* W1   = (const float*)d_in[4];
    const float* b1   = (const float*)d_in[5];
    const float* W2   = (const float*)d_in[6];
    const float* b2   = (const float*)d_in[7];
    const float* W3   = (const float*)d_in[8];
    const float* b3   = (const float*)d_in[9];
    const int n = in_sizes[2];
    const int nb = (n + 255)/256;

    k_hist<<<nb,256>>>(t1,t2,n);
    k_prefix<<<1,32>>>(nb);
    k_scatter<<<nb,256>>>(t1,t2,n);

    cudaFuncSetAttribute(velwarp_kernel,
                         cudaFuncAttributeMaxDynamicSharedMemorySize, SMEM_BYTES);
    velwarp_kernel<<<(n+PPC-1)/PPC, THREADS, SMEM_BYTES>>>(
        code, pos, t1, t2, W1, b1, W2, b2, W3, b3, (float*)d_out, n);
}